// round 1
// baseline (speedup 1.0000x reference)
#include <cuda_runtime.h>
#include <cuda_bf16.h>
#include <math.h>

// Problem constants
#define NB 4
#define LSEQ 2048
#define DM 1024
#define NHEAD 16
#define HD 64               // head dim (D == K == 64)
#define MROWS (NB * LSEQ)   // 8192
#define CH 64               // chunk length
#define NC (LSEQ / CH)      // 32 chunks
#define NH (NB * NHEAD)     // 64 (batch*head)

// Scratch (device globals; no allocation allowed)
__device__ float g_qp[MROWS * DM];     // elu(q)+1
__device__ float g_kp[MROWS * DM];     // elu(k)+1
__device__ float g_v [MROWS * DM];     // v projection
__device__ float g_att[MROWS * DM];    // attention output (pre-Wo)
__device__ float g_S [NH * NC * HD * HD]; // per-chunk K^T V sums -> exclusive prefix
__device__ float g_qs[NH * NC * HD];      // per-chunk qp column sums -> exclusive prefix

// ---------------------------------------------------------------------------
// SGEMM: C[M,1024] = A[M,1024] @ W[1024,1024] + bias, optional elu+1
// BM=128 BN=128 BK=8, 256 threads, 8x8 per thread (split 4+4 register layout)
// ---------------------------------------------------------------------------
__global__ void __launch_bounds__(256) sgemm_bias_act(
    const float* __restrict__ A, const float* __restrict__ W,
    const float* __restrict__ bias, float* __restrict__ C, int act)
{
    __shared__ float As[8][128];
    __shared__ float Bs[8][128];

    const int tid = threadIdx.x;
    const int tx = tid & 15;        // 0..15
    const int ty = tid >> 4;        // 0..15
    const int rowBase = blockIdx.y * 128;
    const int colBase = blockIdx.x * 128;

    const int aRow = tid >> 1;          // 0..127
    const int aCol = (tid & 1) * 4;     // 0 or 4
    const int bRow = tid >> 5;          // 0..7
    const int bCol = (tid & 31) * 4;    // 0..124

    const float* Aptr = A + (size_t)(rowBase + aRow) * DM + aCol;
    const float* Wptr = W + (size_t)bRow * DM + colBase + bCol;

    float acc[8][8];
#pragma unroll
    for (int i = 0; i < 8; i++)
#pragma unroll
        for (int j = 0; j < 8; j++) acc[i][j] = 0.f;

    for (int k0 = 0; k0 < DM; k0 += 8) {
        float4 av = *(const float4*)(Aptr + k0);
        As[aCol + 0][aRow] = av.x;
        As[aCol + 1][aRow] = av.y;
        As[aCol + 2][aRow] = av.z;
        As[aCol + 3][aRow] = av.w;
        *(float4*)&Bs[bRow][bCol] = *(const float4*)(Wptr + (size_t)k0 * DM);
        __syncthreads();

#pragma unroll
        for (int kk = 0; kk < 8; kk++) {
            float ra[8], rb[8];
            float4 a0 = *(const float4*)&As[kk][ty * 4];
            float4 a1 = *(const float4*)&As[kk][64 + ty * 4];
            ra[0]=a0.x; ra[1]=a0.y; ra[2]=a0.z; ra[3]=a0.w;
            ra[4]=a1.x; ra[5]=a1.y; ra[6]=a1.z; ra[7]=a1.w;
            float4 b0 = *(const float4*)&Bs[kk][tx * 4];
            float4 b1 = *(const float4*)&Bs[kk][64 + tx * 4];
            rb[0]=b0.x; rb[1]=b0.y; rb[2]=b0.z; rb[3]=b0.w;
            rb[4]=b1.x; rb[5]=b1.y; rb[6]=b1.z; rb[7]=b1.w;
#pragma unroll
            for (int i = 0; i < 8; i++)
#pragma unroll
                for (int j = 0; j < 8; j++)
                    acc[i][j] = fmaf(ra[i], rb[j], acc[i][j]);
        }
        __syncthreads();
    }

    // epilogue
#pragma unroll
    for (int i = 0; i < 8; i++) {
        int row = rowBase + ((i < 4) ? (ty * 4 + i) : (64 + ty * 4 + i - 4));
#pragma unroll
        for (int jh = 0; jh < 2; jh++) {
            int col0 = colBase + jh * 64 + tx * 4;
            float4 b4 = *(const float4*)(bias + col0);
            float v0 = acc[i][jh * 4 + 0] + b4.x;
            float v1 = acc[i][jh * 4 + 1] + b4.y;
            float v2 = acc[i][jh * 4 + 2] + b4.z;
            float v3 = acc[i][jh * 4 + 3] + b4.w;
            if (act) {
                v0 = (v0 > 0.f) ? (v0 + 1.f) : expf(v0);
                v1 = (v1 > 0.f) ? (v1 + 1.f) : expf(v1);
                v2 = (v2 > 0.f) ? (v2 + 1.f) : expf(v2);
                v3 = (v3 > 0.f) ? (v3 + 1.f) : expf(v3);
            }
            float4 o; o.x=v0; o.y=v1; o.z=v2; o.w=v3;
            *(float4*)(C + (size_t)row * DM + col0) = o;
        }
    }
}

// ---------------------------------------------------------------------------
// Kernel A: per (nh, chunk) compute S_c = Kp_c^T @ V_c  (64x64, sum over 64 rows)
// plus qp column sums. grid (NC, NH), 256 threads.
// ---------------------------------------------------------------------------
__global__ void __launch_bounds__(256) chunk_sums_kernel()
{
    const int c = blockIdx.x;
    const int nh = blockIdx.y;
    const int n = nh >> 4;
    const int h = nh & 15;
    const int tid = threadIdx.x;

    __shared__ float Ks[64][68];
    __shared__ float Vs[64][68];

    const size_t rowbase = ((size_t)(n * LSEQ + c * CH)) * DM + h * HD;

#pragma unroll
    for (int rep = 0; rep < 4; rep++) {
        int idx = rep * 256 + tid;      // 0..1023 float4 slots
        int i  = idx >> 4;
        int j4 = (idx & 15) * 4;
        *(float4*)&Ks[i][j4] = *(const float4*)(g_kp + rowbase + (size_t)i * DM + j4);
        *(float4*)&Vs[i][j4] = *(const float4*)(g_v  + rowbase + (size_t)i * DM + j4);
    }
    __syncthreads();

    const int td = (tid >> 4) * 4;      // d block
    const int tk = (tid & 15) * 4;      // k block
    float acc[4][4];
#pragma unroll
    for (int a = 0; a < 4; a++)
#pragma unroll
        for (int b = 0; b < 4; b++) acc[a][b] = 0.f;

    for (int i = 0; i < 64; i++) {
        float ka[4];
        ka[0] = Ks[i][td + 0]; ka[1] = Ks[i][td + 1];
        ka[2] = Ks[i][td + 2]; ka[3] = Ks[i][td + 3];
        float4 vv = *(const float4*)&Vs[i][tk];
        float vb[4] = {vv.x, vv.y, vv.z, vv.w};
#pragma unroll
        for (int a = 0; a < 4; a++)
#pragma unroll
            for (int b = 0; b < 4; b++)
                acc[a][b] = fmaf(ka[a], vb[b], acc[a][b]);
    }

    float* Sp = g_S + ((size_t)nh * NC + c) * (HD * HD);
#pragma unroll
    for (int a = 0; a < 4; a++) {
        float4 o; o.x=acc[a][0]; o.y=acc[a][1]; o.z=acc[a][2]; o.w=acc[a][3];
        *(float4*)&Sp[(td + a) * HD + tk] = o;
    }

    // qp column sums for this chunk
    if (tid < 64) {
        float s = 0.f;
        for (int i = 0; i < 64; i++)
            s += g_qp[rowbase + (size_t)i * DM + tid];
        g_qs[((size_t)nh * NC + c) * HD + tid] = s;
    }
}

// ---------------------------------------------------------------------------
// Kernel B: exclusive prefix over chunks (in place), per nh. grid 64, 256 thr.
// ---------------------------------------------------------------------------
__global__ void __launch_bounds__(256) prefix_kernel()
{
    const int nh = blockIdx.x;
    const int tid = threadIdx.x;

    float run[16];
#pragma unroll
    for (int e = 0; e < 16; e++) run[e] = 0.f;

    for (int c = 0; c < NC; c++) {
        float* Sp = g_S + ((size_t)nh * NC + c) * (HD * HD);
#pragma unroll
        for (int e = 0; e < 16; e++) {
            int idx = e * 256 + tid;
            float t = Sp[idx];
            Sp[idx] = run[e];
            run[e] += t;
        }
    }

    if (tid < 64) {
        float r = 0.f;
        for (int c = 0; c < NC; c++) {
            float* qp = g_qs + ((size_t)nh * NC + c) * HD + tid;
            float t = *qp;
            *qp = r;
            r += t;
        }
    }
}

// ---------------------------------------------------------------------------
// Kernel C: per (nh, chunk): O = tril(Qp Kp^T) @ V + Qp @ P, divided by Z.
// grid (NC, NH), 256 threads, dynamic shared 5*64*68 floats.
// ---------------------------------------------------------------------------
#define TS (64 * 68)
__global__ void __launch_bounds__(256) chunk_out_kernel()
{
    extern __shared__ float smem[];
    float* Qs = smem;              // [i][d]
    float* Kt = smem + TS;         // [d][i], later reused as Zc [i][k]
    float* Vs = smem + 2 * TS;     // [j][k]
    float* Ps = smem + 3 * TS;     // [d][k]
    float* As = smem + 4 * TS;     // [i][j]

    const int c = blockIdx.x;
    const int nh = blockIdx.y;
    const int n = nh >> 4;
    const int h = nh & 15;
    const int tid = threadIdx.x;

    const size_t rowbase = ((size_t)(n * LSEQ + c * CH)) * DM + h * HD;
    const float* Sp = g_S + ((size_t)nh * NC + c) * (HD * HD);

#pragma unroll
    for (int rep = 0; rep < 4; rep++) {
        int idx = rep * 256 + tid;      // 0..1023
        int i  = idx >> 4;
        int j4 = (idx & 15) * 4;
        float4 q = *(const float4*)(g_qp + rowbase + (size_t)i * DM + j4);
        *(float4*)&Qs[i * 68 + j4] = q;
        float4 k = *(const float4*)(g_kp + rowbase + (size_t)i * DM + j4);
        Kt[(j4 + 0) * 68 + i] = k.x;
        Kt[(j4 + 1) * 68 + i] = k.y;
        Kt[(j4 + 2) * 68 + i] = k.z;
        Kt[(j4 + 3) * 68 + i] = k.w;
        float4 v = *(const float4*)(g_v + rowbase + (size_t)i * DM + j4);
        *(float4*)&Vs[i * 68 + j4] = v;
        float4 p = *(const float4*)(Sp + idx * 4);
        // idx*4 element offset: d = (idx*4)>>6, k = (idx*4)&63
        int d = (idx * 4) >> 6;
        int kk = (idx * 4) & 63;
        *(float4*)&Ps[d * 68 + kk] = p;
    }
    __syncthreads();

    const int ti = (tid >> 4) * 4;
    const int tj = (tid & 15) * 4;

    // A = Qp @ Kp^T with causal mask (j <= i)
    {
        float acc[4][4];
#pragma unroll
        for (int a = 0; a < 4; a++)
#pragma unroll
            for (int b = 0; b < 4; b++) acc[a][b] = 0.f;
        for (int d = 0; d < 64; d++) {
            float qa[4];
            qa[0] = Qs[(ti + 0) * 68 + d]; qa[1] = Qs[(ti + 1) * 68 + d];
            qa[2] = Qs[(ti + 2) * 68 + d]; qa[3] = Qs[(ti + 3) * 68 + d];
            float4 kb = *(const float4*)&Kt[d * 68 + tj];
            float kv[4] = {kb.x, kb.y, kb.z, kb.w};
#pragma unroll
            for (int a = 0; a < 4; a++)
#pragma unroll
                for (int b = 0; b < 4; b++)
                    acc[a][b] = fmaf(qa[a], kv[b], acc[a][b]);
        }
#pragma unroll
        for (int a = 0; a < 4; a++) {
            float4 o;
            o.x = (tj + 0 <= ti + a) ? acc[a][0] : 0.f;
            o.y = (tj + 1 <= ti + a) ? acc[a][1] : 0.f;
            o.z = (tj + 2 <= ti + a) ? acc[a][2] : 0.f;
            o.w = (tj + 3 <= ti + a) ? acc[a][3] : 0.f;
            *(float4*)&As[(ti + a) * 68 + tj] = o;
        }
    }
    __syncthreads();

    // Zc cumsum into Kt region: Z[i][k] = qs_prefix[k] + sum_{i'<=i} Qs[i'][k]
    float* Zc = Kt;
    if (tid < 64) {
        float z = g_qs[((size_t)nh * NC + c) * HD + tid];
        for (int i = 0; i < 64; i++) {
            z += Qs[i * 68 + tid];
            Zc[i * 68 + tid] = z;
        }
    }
    __syncthreads();

    // O = As @ V + Qp @ P, then divide by Zc
    {
        const int tk = tj;
        float acc[4][4];
#pragma unroll
        for (int a = 0; a < 4; a++)
#pragma unroll
            for (int b = 0; b < 4; b++) acc[a][b] = 0.f;

        for (int j = 0; j < 64; j++) {
            float aa[4];
            aa[0] = As[(ti + 0) * 68 + j]; aa[1] = As[(ti + 1) * 68 + j];
            aa[2] = As[(ti + 2) * 68 + j]; aa[3] = As[(ti + 3) * 68 + j];
            float4 vv = *(const float4*)&Vs[j * 68 + tk];
            float vb[4] = {vv.x, vv.y, vv.z, vv.w};
#pragma unroll
            for (int a = 0; a < 4; a++)
#pragma unroll
                for (int b = 0; b < 4; b++)
                    acc[a][b] = fmaf(aa[a], vb[b], acc[a][b]);
        }
        for (int d = 0; d < 64; d++) {
            float qa[4];
            qa[0] = Qs[(ti + 0) * 68 + d]; qa[1] = Qs[(ti + 1) * 68 + d];
            qa[2] = Qs[(ti + 2) * 68 + d]; qa[3] = Qs[(ti + 3) * 68 + d];
            float4 pp = *(const float4*)&Ps[d * 68 + tk];
            float pb[4] = {pp.x, pp.y, pp.z, pp.w};
#pragma unroll
            for (int a = 0; a < 4; a++)
#pragma unroll
                for (int b = 0; b < 4; b++)
                    acc[a][b] = fmaf(qa[a], pb[b], acc[a][b]);
        }

#pragma unroll
        for (int a = 0; a < 4; a++) {
            float4 z4 = *(const float4*)&Zc[(ti + a) * 68 + tk];
            float4 o;
            o.x = acc[a][0] / z4.x;
            o.y = acc[a][1] / z4.y;
            o.z = acc[a][2] / z4.z;
            o.w = acc[a][3] / z4.w;
            *(float4*)(g_att + rowbase + (size_t)(ti + a) * DM + tk) = o;
        }
    }
}

// ---------------------------------------------------------------------------
extern "C" void kernel_launch(void* const* d_in, const int* in_sizes, int n_in,
                              void* d_out, int out_size)
{
    const float* queries = (const float*)d_in[0];
    const float* keys    = (const float*)d_in[1];
    const float* values  = (const float*)d_in[2];
    const float* Wq = (const float*)d_in[3];
    const float* bq = (const float*)d_in[4];
    const float* Wk = (const float*)d_in[5];
    const float* bk = (const float*)d_in[6];
    const float* Wv = (const float*)d_in[7];
    const float* bv = (const float*)d_in[8];
    const float* Wo = (const float*)d_in[9];
    const float* bo = (const float*)d_in[10];
    float* out = (float*)d_out;

    float* qp;  cudaGetSymbolAddress((void**)&qp,  g_qp);
    float* kp;  cudaGetSymbolAddress((void**)&kp,  g_kp);
    float* vv;  cudaGetSymbolAddress((void**)&vv,  g_v);
    float* att; cudaGetSymbolAddress((void**)&att, g_att);

    dim3 gemmGrid(DM / 128, MROWS / 128);
    dim3 gemmBlock(256);

    // Projections (q,k with elu+1; v plain)
    sgemm_bias_act<<<gemmGrid, gemmBlock>>>(queries, Wq, bq, qp, 1);
    sgemm_bias_act<<<gemmGrid, gemmBlock>>>(keys,    Wk, bk, kp, 1);
    sgemm_bias_act<<<gemmGrid, gemmBlock>>>(values,  Wv, bv, vv, 0);

    // Chunked causal linear attention
    dim3 chunkGrid(NC, NH);
    chunk_sums_kernel<<<chunkGrid, 256>>>();
    prefix_kernel<<<NH, 256>>>();

    static const size_t smemBytes = 5 * TS * sizeof(float); // 87040
    cudaFuncSetAttribute(chunk_out_kernel,
                         cudaFuncAttributeMaxDynamicSharedMemorySize,
                         (int)smemBytes);
    chunk_out_kernel<<<chunkGrid, 256, smemBytes>>>();

    // Output projection
    sgemm_bias_act<<<gemmGrid, gemmBlock>>>(att, Wo, bo, out, 0);
}

// round 3
// speedup vs baseline: 1.7965x; 1.7965x over previous
#include <cuda_runtime.h>
#include <cuda_bf16.h>
#include <math.h>
#include <cstdint>

// Problem constants
#define NB 4
#define LSEQ 2048
#define DM 1024
#define NHEAD 16
#define HD 64
#define MROWS (NB * LSEQ)   // 8192
#define CH 64
#define NC (LSEQ / CH)      // 32
#define NH (NB * NHEAD)     // 64

// Scratch (device globals; no allocation allowed)
__device__ float g_qp[MROWS * DM];
__device__ float g_kp[MROWS * DM];
__device__ float g_v [MROWS * DM];
__device__ float g_att[MROWS * DM];
__device__ float g_S [NH * NC * HD * HD];
__device__ float g_qs[NH * NC * HD];

// bf16 split scratch
__device__ __nv_bfloat16 g_Ahi[MROWS * DM];
__device__ __nv_bfloat16 g_Alo[MROWS * DM];
__device__ __nv_bfloat16 g_Whi[DM * DM];   // transposed: [n][k]
__device__ __nv_bfloat16 g_Wlo[DM * DM];   // transposed: [n][k]

// ---------------------------------------------------------------------------
// PTX helpers
// ---------------------------------------------------------------------------
__device__ __forceinline__ uint32_t smem_u32(const void* p) {
    uint32_t a;
    asm("{ .reg .u64 t; cvta.to.shared.u64 t, %1; cvt.u32.u64 %0, t; }"
        : "=r"(a) : "l"(p));
    return a;
}

#define CPASYNC16(s, g) \
    asm volatile("cp.async.cg.shared.global [%0], [%1], 16;" \
                 :: "r"(s), "l"(g) : "memory")
#define CPCOMMIT() asm volatile("cp.async.commit_group;" ::: "memory")
#define CPWAIT1()  asm volatile("cp.async.wait_group 1;" ::: "memory")

__device__ __forceinline__ void ldsm4(uint32_t* r, uint32_t a) {
    asm volatile("ldmatrix.sync.aligned.m8n8.x4.shared.b16 {%0,%1,%2,%3}, [%4];"
        : "=r"(r[0]), "=r"(r[1]), "=r"(r[2]), "=r"(r[3]) : "r"(a));
}
__device__ __forceinline__ void ldsm2(uint32_t* r, uint32_t a) {
    asm volatile("ldmatrix.sync.aligned.m8n8.x2.shared.b16 {%0,%1}, [%2];"
        : "=r"(r[0]), "=r"(r[1]) : "r"(a));
}
__device__ __forceinline__ void mma16816(float* c, const uint32_t* a, const uint32_t* b) {
    asm volatile("mma.sync.aligned.m16n8k16.row.col.f32.bf16.bf16.f32 "
        "{%0,%1,%2,%3}, {%4,%5,%6,%7}, {%8,%9}, {%0,%1,%2,%3};"
        : "+f"(c[0]), "+f"(c[1]), "+f"(c[2]), "+f"(c[3])
        : "r"(a[0]), "r"(a[1]), "r"(a[2]), "r"(a[3]), "r"(b[0]), "r"(b[1]));
}

// ---------------------------------------------------------------------------
// Split kernels: fp32 -> (hi, lo) bf16
// ---------------------------------------------------------------------------
__global__ void __launch_bounds__(256) split_input(
    const float* __restrict__ X, __nv_bfloat16* __restrict__ hi,
    __nv_bfloat16* __restrict__ lo, int n4)
{
    int idx = blockIdx.x * 256 + threadIdx.x;
    if (idx >= n4) return;
    float4 x = ((const float4*)X)[idx];
    __nv_bfloat16 h0 = __float2bfloat16(x.x);
    __nv_bfloat16 h1 = __float2bfloat16(x.y);
    __nv_bfloat16 h2 = __float2bfloat16(x.z);
    __nv_bfloat16 h3 = __float2bfloat16(x.w);
    __nv_bfloat16 l0 = __float2bfloat16(x.x - __bfloat162float(h0));
    __nv_bfloat16 l1 = __float2bfloat16(x.y - __bfloat162float(h1));
    __nv_bfloat16 l2 = __float2bfloat16(x.z - __bfloat162float(h2));
    __nv_bfloat16 l3 = __float2bfloat16(x.w - __bfloat162float(h3));
    __nv_bfloat162* hp = (__nv_bfloat162*)hi;
    __nv_bfloat162* lp = (__nv_bfloat162*)lo;
    hp[idx * 2 + 0] = __nv_bfloat162(h0, h1);
    hp[idx * 2 + 1] = __nv_bfloat162(h2, h3);
    lp[idx * 2 + 0] = __nv_bfloat162(l0, l1);
    lp[idx * 2 + 1] = __nv_bfloat162(l2, l3);
}

// Transpose + split weights: W[k][n] fp32 -> Wt_hi/lo [n][k] bf16
__global__ void __launch_bounds__(256) transpose_split(
    const float* __restrict__ W, __nv_bfloat16* __restrict__ hi,
    __nv_bfloat16* __restrict__ lo)
{
    __shared__ float t[32][33];
    int bx = blockIdx.x * 32;   // n base
    int by = blockIdx.y * 32;   // k base
    int tx = threadIdx.x & 31;
    int ty = threadIdx.x >> 5;  // 0..7
#pragma unroll
    for (int i = 0; i < 4; i++) {
        int k = by + ty + i * 8;
        t[ty + i * 8][tx] = W[(size_t)k * DM + bx + tx];
    }
    __syncthreads();
#pragma unroll
    for (int i = 0; i < 4; i++) {
        int n = bx + ty + i * 8;
        int k = by + tx;
        float v = t[tx][ty + i * 8];
        __nv_bfloat16 h = __float2bfloat16(v);
        __nv_bfloat16 l = __float2bfloat16(v - __bfloat162float(h));
        hi[(size_t)n * DM + k] = h;
        lo[(size_t)n * DM + k] = l;
    }
}

// ---------------------------------------------------------------------------
// Tensor-core GEMM via mma.sync (bf16, 3-term split):
// C[8192,1024] = A @ W + bias (+elu+1)
// BM=BN=128, BK=32, 256 threads, warp tile 64x32, cp.async 3-stage pipeline.
// smem rows padded to 80B for conflict-free ldmatrix.
// ---------------------------------------------------------------------------
#define STG 40960            // bytes per stage (4 arrays * 128 rows * 80B)
#define ARR 10240            // bytes per array within a stage
#define NSTAGE 3
#define GEMM_SMEM (NSTAGE * STG)

__device__ __forceinline__ void load_stage(
    uint32_t sbase, int tid, int k0,
    const __nv_bfloat16* pAhi, const __nv_bfloat16* pAlo,
    const __nv_bfloat16* pWhi, const __nv_bfloat16* pWlo)
{
#pragma unroll
    for (int rep = 0; rep < 2; rep++) {
        int l = rep * 256 + tid;        // 0..511
        int row = l >> 2;               // 0..127
        int ch = l & 3;                 // 0..3 (16B chunks)
        uint32_t so = sbase + (uint32_t)row * 80 + ch * 16;
        size_t go = (size_t)row * DM + k0 + ch * 8;
        CPASYNC16(so + 0 * ARR, pAhi + go);
        CPASYNC16(so + 1 * ARR, pAlo + go);
        CPASYNC16(so + 2 * ARR, pWhi + go);
        CPASYNC16(so + 3 * ARR, pWlo + go);
    }
}

__global__ void __launch_bounds__(256) gemm_mma(
    const __nv_bfloat16* __restrict__ Ahi, const __nv_bfloat16* __restrict__ Alo,
    const __nv_bfloat16* __restrict__ Whi, const __nv_bfloat16* __restrict__ Wlo,
    const float* __restrict__ bias, float* __restrict__ C, int act)
{
    extern __shared__ char smem[];
    const uint32_t sb = smem_u32(smem);
    const int tid = threadIdx.x;
    const int wid = tid >> 5;
    const int lid = tid & 31;
    const int rowBase = blockIdx.y * 128;
    const int colBase = blockIdx.x * 128;
    const int warpM = (wid >> 2) * 64;   // 0 or 64
    const int warpN = (wid & 3) * 32;    // 0,32,64,96

    const __nv_bfloat16* pAhi = Ahi + (size_t)rowBase * DM;
    const __nv_bfloat16* pAlo = Alo + (size_t)rowBase * DM;
    const __nv_bfloat16* pWhi = Whi + (size_t)colBase * DM;
    const __nv_bfloat16* pWlo = Wlo + (size_t)colBase * DM;

    float acc[4][4][4];
#pragma unroll
    for (int i = 0; i < 4; i++)
#pragma unroll
        for (int j = 0; j < 4; j++)
#pragma unroll
            for (int e = 0; e < 4; e++) acc[i][j][e] = 0.f;

    // prologue: stages 0, 1
    load_stage(sb + 0 * STG, tid, 0, pAhi, pAlo, pWhi, pWlo);
    CPCOMMIT();
    load_stage(sb + 1 * STG, tid, 32, pAhi, pAlo, pWhi, pWlo);
    CPCOMMIT();

    // lane-invariant pieces of ldmatrix addressing
    const int aRow = warpM + (lid & 15);          // + mi*16
    const uint32_t aCol = ((lid >> 4) & 1) * 16;  // + kk*32
    const int bRow = warpN + (lid & 7);           // + ni*8
    const uint32_t bCol = ((lid >> 3) & 1) * 16;  // + kk*32

    for (int c = 0; c < 32; c++) {
        CPWAIT1();
        __syncthreads();

        // issue stage c+2
        if (c + 2 < 32)
            load_stage(sb + ((c + 2) % NSTAGE) * STG, tid, (c + 2) * 32,
                       pAhi, pAlo, pWhi, pWlo);
        CPCOMMIT();

        const uint32_t stage = sb + (c % NSTAGE) * STG;
#pragma unroll
        for (int kk = 0; kk < 2; kk++) {
            uint32_t fAhi[4][4], fAlo[4][4];
            uint32_t fBhi[4][2], fBlo[4][2];
            const uint32_t aOff = (uint32_t)kk * 32 + aCol;
            const uint32_t bOff = (uint32_t)kk * 32 + bCol;
#pragma unroll
            for (int mi = 0; mi < 4; mi++) {
                uint32_t ad = stage + (uint32_t)(aRow + mi * 16) * 80 + aOff;
                ldsm4(fAhi[mi], ad + 0 * ARR);
                ldsm4(fAlo[mi], ad + 1 * ARR);
            }
#pragma unroll
            for (int ni = 0; ni < 4; ni++) {
                uint32_t bd = stage + (uint32_t)(bRow + ni * 8) * 80 + bOff;
                ldsm2(fBhi[ni], bd + 2 * ARR);
                ldsm2(fBlo[ni], bd + 3 * ARR);
            }
#pragma unroll
            for (int mi = 0; mi < 4; mi++)
#pragma unroll
                for (int ni = 0; ni < 4; ni++) {
                    mma16816(acc[mi][ni], fAhi[mi], fBhi[ni]);
                    mma16816(acc[mi][ni], fAhi[mi], fBlo[ni]);
                    mma16816(acc[mi][ni], fAlo[mi], fBhi[ni]);
                }
        }
    }

    // epilogue: bias + optional elu+1, write fp32
#pragma unroll
    for (int mi = 0; mi < 4; mi++) {
        int r0 = rowBase + warpM + mi * 16 + (lid >> 2);
#pragma unroll
        for (int ni = 0; ni < 4; ni++) {
            int col = colBase + warpN + ni * 8 + (lid & 3) * 2;
            float2 b2 = *(const float2*)(bias + col);
            float v0 = acc[mi][ni][0] + b2.x;
            float v1 = acc[mi][ni][1] + b2.y;
            float v2 = acc[mi][ni][2] + b2.x;
            float v3 = acc[mi][ni][3] + b2.y;
            if (act) {
                v0 = (v0 > 0.f) ? (v0 + 1.f) : expf(v0);
                v1 = (v1 > 0.f) ? (v1 + 1.f) : expf(v1);
                v2 = (v2 > 0.f) ? (v2 + 1.f) : expf(v2);
                v3 = (v3 > 0.f) ? (v3 + 1.f) : expf(v3);
            }
            float2 o0; o0.x = v0; o0.y = v1;
            float2 o1; o1.x = v2; o1.y = v3;
            *(float2*)(C + (size_t)r0 * DM + col) = o0;
            *(float2*)(C + (size_t)(r0 + 8) * DM + col) = o1;
        }
    }
}

// ---------------------------------------------------------------------------
// Attention kernels (unchanged from R1)
// ---------------------------------------------------------------------------
__global__ void __launch_bounds__(256) chunk_sums_kernel()
{
    const int c = blockIdx.x;
    const int nh = blockIdx.y;
    const int n = nh >> 4;
    const int h = nh & 15;
    const int tid = threadIdx.x;

    __shared__ float Ks[64][68];
    __shared__ float Vs[64][68];

    const size_t rowbase = ((size_t)(n * LSEQ + c * CH)) * DM + h * HD;

#pragma unroll
    for (int rep = 0; rep < 4; rep++) {
        int idx = rep * 256 + tid;
        int i  = idx >> 4;
        int j4 = (idx & 15) * 4;
        *(float4*)&Ks[i][j4] = *(const float4*)(g_kp + rowbase + (size_t)i * DM + j4);
        *(float4*)&Vs[i][j4] = *(const float4*)(g_v  + rowbase + (size_t)i * DM + j4);
    }
    __syncthreads();

    const int td = (tid >> 4) * 4;
    const int tk = (tid & 15) * 4;
    float acc[4][4];
#pragma unroll
    for (int a = 0; a < 4; a++)
#pragma unroll
        for (int b = 0; b < 4; b++) acc[a][b] = 0.f;

    for (int i = 0; i < 64; i++) {
        float ka[4];
        ka[0] = Ks[i][td + 0]; ka[1] = Ks[i][td + 1];
        ka[2] = Ks[i][td + 2]; ka[3] = Ks[i][td + 3];
        float4 vv = *(const float4*)&Vs[i][tk];
        float vb[4] = {vv.x, vv.y, vv.z, vv.w};
#pragma unroll
        for (int a = 0; a < 4; a++)
#pragma unroll
            for (int b = 0; b < 4; b++)
                acc[a][b] = fmaf(ka[a], vb[b], acc[a][b]);
    }

    float* Sp = g_S + ((size_t)nh * NC + c) * (HD * HD);
#pragma unroll
    for (int a = 0; a < 4; a++) {
        float4 o; o.x=acc[a][0]; o.y=acc[a][1]; o.z=acc[a][2]; o.w=acc[a][3];
        *(float4*)&Sp[(td + a) * HD + tk] = o;
    }

    if (tid < 64) {
        float s = 0.f;
        for (int i = 0; i < 64; i++)
            s += g_qp[rowbase + (size_t)i * DM + tid];
        g_qs[((size_t)nh * NC + c) * HD + tid] = s;
    }
}

__global__ void __launch_bounds__(256) prefix_kernel()
{
    const int nh = blockIdx.x;
    const int tid = threadIdx.x;

    float run[16];
#pragma unroll
    for (int e = 0; e < 16; e++) run[e] = 0.f;

    for (int c = 0; c < NC; c++) {
        float* Sp = g_S + ((size_t)nh * NC + c) * (HD * HD);
#pragma unroll
        for (int e = 0; e < 16; e++) {
            int idx = e * 256 + tid;
            float t = Sp[idx];
            Sp[idx] = run[e];
            run[e] += t;
        }
    }

    if (tid < 64) {
        float r = 0.f;
        for (int c = 0; c < NC; c++) {
            float* qp = g_qs + ((size_t)nh * NC + c) * HD + tid;
            float t = *qp;
            *qp = r;
            r += t;
        }
    }
}

#define TS (64 * 68)
__global__ void __launch_bounds__(256) chunk_out_kernel()
{
    extern __shared__ float fsm[];
    float* Qs = fsm;
    float* Kt = fsm + TS;
    float* Vs = fsm + 2 * TS;
    float* Ps = fsm + 3 * TS;
    float* As = fsm + 4 * TS;

    const int c = blockIdx.x;
    const int nh = blockIdx.y;
    const int n = nh >> 4;
    const int h = nh & 15;
    const int tid = threadIdx.x;

    const size_t rowbase = ((size_t)(n * LSEQ + c * CH)) * DM + h * HD;
    const float* Sp = g_S + ((size_t)nh * NC + c) * (HD * HD);

#pragma unroll
    for (int rep = 0; rep < 4; rep++) {
        int idx = rep * 256 + tid;
        int i  = idx >> 4;
        int j4 = (idx & 15) * 4;
        float4 q = *(const float4*)(g_qp + rowbase + (size_t)i * DM + j4);
        *(float4*)&Qs[i * 68 + j4] = q;
        float4 k = *(const float4*)(g_kp + rowbase + (size_t)i * DM + j4);
        Kt[(j4 + 0) * 68 + i] = k.x;
        Kt[(j4 + 1) * 68 + i] = k.y;
        Kt[(j4 + 2) * 68 + i] = k.z;
        Kt[(j4 + 3) * 68 + i] = k.w;
        float4 v = *(const float4*)(g_v + rowbase + (size_t)i * DM + j4);
        *(float4*)&Vs[i * 68 + j4] = v;
        float4 p = *(const float4*)(Sp + idx * 4);
        int d = (idx * 4) >> 6;
        int kk = (idx * 4) & 63;
        *(float4*)&Ps[d * 68 + kk] = p;
    }
    __syncthreads();

    const int ti = (tid >> 4) * 4;
    const int tj = (tid & 15) * 4;

    {
        float acc[4][4];
#pragma unroll
        for (int a = 0; a < 4; a++)
#pragma unroll
            for (int b = 0; b < 4; b++) acc[a][b] = 0.f;
        for (int d = 0; d < 64; d++) {
            float qa[4];
            qa[0] = Qs[(ti + 0) * 68 + d]; qa[1] = Qs[(ti + 1) * 68 + d];
            qa[2] = Qs[(ti + 2) * 68 + d]; qa[3] = Qs[(ti + 3) * 68 + d];
            float4 kb = *(const float4*)&Kt[d * 68 + tj];
            float kv[4] = {kb.x, kb.y, kb.z, kb.w};
#pragma unroll
            for (int a = 0; a < 4; a++)
#pragma unroll
                for (int b = 0; b < 4; b++)
                    acc[a][b] = fmaf(qa[a], kv[b], acc[a][b]);
        }
#pragma unroll
        for (int a = 0; a < 4; a++) {
            float4 o;
            o.x = (tj + 0 <= ti + a) ? acc[a][0] : 0.f;
            o.y = (tj + 1 <= ti + a) ? acc[a][1] : 0.f;
            o.z = (tj + 2 <= ti + a) ? acc[a][2] : 0.f;
            o.w = (tj + 3 <= ti + a) ? acc[a][3] : 0.f;
            *(float4*)&As[(ti + a) * 68 + tj] = o;
        }
    }
    __syncthreads();

    float* Zc = Kt;
    if (tid < 64) {
        float z = g_qs[((size_t)nh * NC + c) * HD + tid];
        for (int i = 0; i < 64; i++) {
            z += Qs[i * 68 + tid];
            Zc[i * 68 + tid] = z;
        }
    }
    __syncthreads();

    {
        const int tk = tj;
        float acc[4][4];
#pragma unroll
        for (int a = 0; a < 4; a++)
#pragma unroll
            for (int b = 0; b < 4; b++) acc[a][b] = 0.f;

        for (int j = 0; j < 64; j++) {
            float aa[4];
            aa[0] = As[(ti + 0) * 68 + j]; aa[1] = As[(ti + 1) * 68 + j];
            aa[2] = As[(ti + 2) * 68 + j]; aa[3] = As[(ti + 3) * 68 + j];
            float4 vv = *(const float4*)&Vs[j * 68 + tk];
            float vb[4] = {vv.x, vv.y, vv.z, vv.w};
#pragma unroll
            for (int a = 0; a < 4; a++)
#pragma unroll
                for (int b = 0; b < 4; b++)
                    acc[a][b] = fmaf(aa[a], vb[b], acc[a][b]);
        }
        for (int d = 0; d < 64; d++) {
            float qa[4];
            qa[0] = Qs[(ti + 0) * 68 + d]; qa[1] = Qs[(ti + 1) * 68 + d];
            qa[2] = Qs[(ti + 2) * 68 + d]; qa[3] = Qs[(ti + 3) * 68 + d];
            float4 pp = *(const float4*)&Ps[d * 68 + tk];
            float pb[4] = {pp.x, pp.y, pp.z, pp.w};
#pragma unroll
            for (int a = 0; a < 4; a++)
#pragma unroll
                for (int b = 0; b < 4; b++)
                    acc[a][b] = fmaf(qa[a], pb[b], acc[a][b]);
        }

#pragma unroll
        for (int a = 0; a < 4; a++) {
            float4 z4 = *(const float4*)&Zc[(ti + a) * 68 + tk];
            float4 o;
            o.x = acc[a][0] / z4.x;
            o.y = acc[a][1] / z4.y;
            o.z = acc[a][2] / z4.z;
            o.w = acc[a][3] / z4.w;
            *(float4*)(g_att + rowbase + (size_t)(ti + a) * DM + tk) = o;
        }
    }
}

// ---------------------------------------------------------------------------
extern "C" void kernel_launch(void* const* d_in, const int* in_sizes, int n_in,
                              void* d_out, int out_size)
{
    const float* queries = (const float*)d_in[0];
    const float* keys    = (const float*)d_in[1];
    const float* values  = (const float*)d_in[2];
    const float* Wq = (const float*)d_in[3];
    const float* bq = (const float*)d_in[4];
    const float* Wk = (const float*)d_in[5];
    const float* bk = (const float*)d_in[6];
    const float* Wv = (const float*)d_in[7];
    const float* bv = (const float*)d_in[8];
    const float* Wo = (const float*)d_in[9];
    const float* bo = (const float*)d_in[10];
    float* out = (float*)d_out;

    float* qp;  cudaGetSymbolAddress((void**)&qp,  g_qp);
    float* kp;  cudaGetSymbolAddress((void**)&kp,  g_kp);
    float* vv;  cudaGetSymbolAddress((void**)&vv,  g_v);
    float* att; cudaGetSymbolAddress((void**)&att, g_att);
    __nv_bfloat16* ahi; cudaGetSymbolAddress((void**)&ahi, g_Ahi);
    __nv_bfloat16* alo; cudaGetSymbolAddress((void**)&alo, g_Alo);
    __nv_bfloat16* whi; cudaGetSymbolAddress((void**)&whi, g_Whi);
    __nv_bfloat16* wlo; cudaGetSymbolAddress((void**)&wlo, g_Wlo);

    static bool attrSet = false;
    if (!attrSet) {
        cudaFuncSetAttribute(gemm_mma, cudaFuncAttributeMaxDynamicSharedMemorySize,
                             GEMM_SMEM);
        cudaFuncSetAttribute(chunk_out_kernel,
                             cudaFuncAttributeMaxDynamicSharedMemorySize,
                             (int)(5 * TS * sizeof(float)));
        attrSet = true;
    }

    const int splitBlocks = (MROWS * DM / 4 + 255) / 256;
    dim3 tsGrid(DM / 32, DM / 32);
    dim3 gemmGrid(DM / 128, MROWS / 128);

    // Q projection
    transpose_split<<<tsGrid, 256>>>(Wq, whi, wlo);
    split_input<<<splitBlocks, 256>>>(queries, ahi, alo, MROWS * DM / 4);
    gemm_mma<<<gemmGrid, 256, GEMM_SMEM>>>(ahi, alo, whi, wlo, bq, qp, 1);

    // K projection
    transpose_split<<<tsGrid, 256>>>(Wk, whi, wlo);
    split_input<<<splitBlocks, 256>>>(keys, ahi, alo, MROWS * DM / 4);
    gemm_mma<<<gemmGrid, 256, GEMM_SMEM>>>(ahi, alo, whi, wlo, bk, kp, 1);

    // V projection
    transpose_split<<<tsGrid, 256>>>(Wv, whi, wlo);
    split_input<<<splitBlocks, 256>>>(values, ahi, alo, MROWS * DM / 4);
    gemm_mma<<<gemmGrid, 256, GEMM_SMEM>>>(ahi, alo, whi, wlo, bv, vv, 0);

    // Chunked causal linear attention
    dim3 chunkGrid(NC, NH);
    chunk_sums_kernel<<<chunkGrid, 256>>>();
    prefix_kernel<<<NH, 256>>>();
    chunk_out_kernel<<<chunkGrid, 256, 5 * TS * sizeof(float)>>>();

    // Output projection
    transpose_split<<<tsGrid, 256>>>(Wo, whi, wlo);
    split_input<<<splitBlocks, 256>>>(att, ahi, alo, MROWS * DM / 4);
    gemm_mma<<<gemmGrid, 256, GEMM_SMEM>>>(ahi, alo, whi, wlo, bo, out, 0);
}

// round 4
// speedup vs baseline: 1.9164x; 1.0667x over previous
#include <cuda_runtime.h>
#include <cuda_bf16.h>
#include <math.h>
#include <cstdint>

// Problem constants
#define NB 4
#define LSEQ 2048
#define DM 1024
#define NHEAD 16
#define HD 64
#define MROWS (NB * LSEQ)   // 8192
#define CH 64
#define NC (LSEQ / CH)      // 32
#define NH (NB * NHEAD)     // 64

// Scratch (device globals; no allocation allowed)
__device__ float g_qp[MROWS * DM];
__device__ float g_kp[MROWS * DM];
__device__ float g_v [MROWS * DM];
__device__ float g_S [NH * NC * HD * HD];
__device__ float g_qs[NH * NC * HD];

// bf16 split scratch
__device__ __nv_bfloat16 g_Ahi[MROWS * DM];
__device__ __nv_bfloat16 g_Alo[MROWS * DM];
__device__ __nv_bfloat16 g_Whi[DM * DM];   // transposed: [n][k]
__device__ __nv_bfloat16 g_Wlo[DM * DM];   // transposed: [n][k]

// ---------------------------------------------------------------------------
// PTX helpers
// ---------------------------------------------------------------------------
__device__ __forceinline__ uint32_t smem_u32(const void* p) {
    uint32_t a;
    asm("{ .reg .u64 t; cvta.to.shared.u64 t, %1; cvt.u32.u64 %0, t; }"
        : "=r"(a) : "l"(p));
    return a;
}

#define CPASYNC16(s, g) \
    asm volatile("cp.async.cg.shared.global [%0], [%1], 16;" \
                 :: "r"(s), "l"(g) : "memory")
#define CPCOMMIT() asm volatile("cp.async.commit_group;" ::: "memory")
#define CPWAIT1()  asm volatile("cp.async.wait_group 1;" ::: "memory")
#define CPWAIT0()  asm volatile("cp.async.wait_group 0;" ::: "memory")

__device__ __forceinline__ void ldsm4(uint32_t* r, uint32_t a) {
    asm volatile("ldmatrix.sync.aligned.m8n8.x4.shared.b16 {%0,%1,%2,%3}, [%4];"
        : "=r"(r[0]), "=r"(r[1]), "=r"(r[2]), "=r"(r[3]) : "r"(a));
}
__device__ __forceinline__ void ldsm2(uint32_t* r, uint32_t a) {
    asm volatile("ldmatrix.sync.aligned.m8n8.x2.shared.b16 {%0,%1}, [%2];"
        : "=r"(r[0]), "=r"(r[1]) : "r"(a));
}
__device__ __forceinline__ void mma16816(float* c, const uint32_t* a, const uint32_t* b) {
    asm volatile("mma.sync.aligned.m16n8k16.row.col.f32.bf16.bf16.f32 "
        "{%0,%1,%2,%3}, {%4,%5,%6,%7}, {%8,%9}, {%0,%1,%2,%3};"
        : "+f"(c[0]), "+f"(c[1]), "+f"(c[2]), "+f"(c[3])
        : "r"(a[0]), "r"(a[1]), "r"(a[2]), "r"(a[3]), "r"(b[0]), "r"(b[1]));
}

// ---------------------------------------------------------------------------
// Split kernels: fp32 -> (hi, lo) bf16
// ---------------------------------------------------------------------------
__global__ void __launch_bounds__(256) split_input(
    const float* __restrict__ X, __nv_bfloat16* __restrict__ hi,
    __nv_bfloat16* __restrict__ lo, int n4)
{
    int idx = blockIdx.x * 256 + threadIdx.x;
    if (idx >= n4) return;
    float4 x = ((const float4*)X)[idx];
    __nv_bfloat16 h0 = __float2bfloat16(x.x);
    __nv_bfloat16 h1 = __float2bfloat16(x.y);
    __nv_bfloat16 h2 = __float2bfloat16(x.z);
    __nv_bfloat16 h3 = __float2bfloat16(x.w);
    __nv_bfloat16 l0 = __float2bfloat16(x.x - __bfloat162float(h0));
    __nv_bfloat16 l1 = __float2bfloat16(x.y - __bfloat162float(h1));
    __nv_bfloat16 l2 = __float2bfloat16(x.z - __bfloat162float(h2));
    __nv_bfloat16 l3 = __float2bfloat16(x.w - __bfloat162float(h3));
    __nv_bfloat162* hp = (__nv_bfloat162*)hi;
    __nv_bfloat162* lp = (__nv_bfloat162*)lo;
    hp[idx * 2 + 0] = __nv_bfloat162(h0, h1);
    hp[idx * 2 + 1] = __nv_bfloat162(h2, h3);
    lp[idx * 2 + 0] = __nv_bfloat162(l0, l1);
    lp[idx * 2 + 1] = __nv_bfloat162(l2, l3);
}

// Transpose + split weights: W[k][n] fp32 -> Wt_hi/lo [n][k] bf16
__global__ void __launch_bounds__(256) transpose_split(
    const float* __restrict__ W, __nv_bfloat16* __restrict__ hi,
    __nv_bfloat16* __restrict__ lo)
{
    __shared__ float t[32][33];
    int bx = blockIdx.x * 32;   // n base
    int by = blockIdx.y * 32;   // k base
    int tx = threadIdx.x & 31;
    int ty = threadIdx.x >> 5;  // 0..7
#pragma unroll
    for (int i = 0; i < 4; i++) {
        int k = by + ty + i * 8;
        t[ty + i * 8][tx] = W[(size_t)k * DM + bx + tx];
    }
    __syncthreads();
#pragma unroll
    for (int i = 0; i < 4; i++) {
        int n = bx + ty + i * 8;
        int k = by + tx;
        float v = t[tx][ty + i * 8];
        __nv_bfloat16 h = __float2bfloat16(v);
        __nv_bfloat16 l = __float2bfloat16(v - __bfloat162float(h));
        hi[(size_t)n * DM + k] = h;
        lo[(size_t)n * DM + k] = l;
    }
}

// ---------------------------------------------------------------------------
// Tensor-core GEMM via mma.sync (bf16, 3-term split):
// C[8192,1024] = A @ W + bias (+elu+1)
// BM=BN=128, BK=32, 256 threads, warp tile 64x32, cp.async 2-stage pipeline,
// 2 CTAs/SM. smem rows padded to 80B for conflict-free ldmatrix.
// ---------------------------------------------------------------------------
#define STG 40960            // bytes per stage (4 arrays * 128 rows * 80B)
#define ARR 10240            // bytes per array within a stage
#define GEMM_SMEM (2 * STG)  // 81920

__device__ __forceinline__ void load_stage(
    uint32_t sbase, int tid, int k0,
    const __nv_bfloat16* pAhi, const __nv_bfloat16* pAlo,
    const __nv_bfloat16* pWhi, const __nv_bfloat16* pWlo)
{
#pragma unroll
    for (int rep = 0; rep < 2; rep++) {
        int l = rep * 256 + tid;        // 0..511
        int row = l >> 2;               // 0..127
        int ch = l & 3;                 // 0..3 (16B chunks)
        uint32_t so = sbase + (uint32_t)row * 80 + ch * 16;
        size_t go = (size_t)row * DM + k0 + ch * 8;
        CPASYNC16(so + 0 * ARR, pAhi + go);
        CPASYNC16(so + 1 * ARR, pAlo + go);
        CPASYNC16(so + 2 * ARR, pWhi + go);
        CPASYNC16(so + 3 * ARR, pWlo + go);
    }
}

__global__ void __launch_bounds__(256, 2) gemm_mma(
    const __nv_bfloat16* __restrict__ Ahi, const __nv_bfloat16* __restrict__ Alo,
    const __nv_bfloat16* __restrict__ Whi, const __nv_bfloat16* __restrict__ Wlo,
    const float* __restrict__ bias, float* __restrict__ C, int act)
{
    extern __shared__ char smem[];
    const uint32_t sb = smem_u32(smem);
    const int tid = threadIdx.x;
    const int wid = tid >> 5;
    const int lid = tid & 31;
    const int rowBase = blockIdx.y * 128;
    const int colBase = blockIdx.x * 128;
    const int warpM = (wid >> 2) * 64;   // 0 or 64
    const int warpN = (wid & 3) * 32;    // 0,32,64,96

    const __nv_bfloat16* pAhi = Ahi + (size_t)rowBase * DM;
    const __nv_bfloat16* pAlo = Alo + (size_t)rowBase * DM;
    const __nv_bfloat16* pWhi = Whi + (size_t)colBase * DM;
    const __nv_bfloat16* pWlo = Wlo + (size_t)colBase * DM;

    float acc[4][4][4];
#pragma unroll
    for (int i = 0; i < 4; i++)
#pragma unroll
        for (int j = 0; j < 4; j++)
#pragma unroll
            for (int e = 0; e < 4; e++) acc[i][j][e] = 0.f;

    // prologue: stage 0
    load_stage(sb, tid, 0, pAhi, pAlo, pWhi, pWlo);
    CPCOMMIT();

    // lane-invariant pieces of ldmatrix addressing
    const int aRow = warpM + (lid & 15);          // + mi*16
    const uint32_t aCol = ((lid >> 4) & 1) * 16;  // + kk*32
    const int bRow = warpN + (lid & 7);           // + ni*8
    const uint32_t bCol = ((lid >> 3) & 1) * 16;  // + kk*32

    for (int c = 0; c < 32; c++) {
        if (c + 1 < 32) {
            load_stage(sb + ((c + 1) & 1) * STG, tid, (c + 1) * 32,
                       pAhi, pAlo, pWhi, pWlo);
            CPCOMMIT();
            CPWAIT1();
        } else {
            CPWAIT0();
        }
        __syncthreads();

        const uint32_t stage = sb + (c & 1) * STG;
#pragma unroll
        for (int kk = 0; kk < 2; kk++) {
            const uint32_t aOff = (uint32_t)kk * 32 + aCol;
            const uint32_t bOff = (uint32_t)kk * 32 + bCol;
            uint32_t fBhi[4][2], fBlo[4][2];
#pragma unroll
            for (int ni = 0; ni < 4; ni++) {
                uint32_t bd = stage + (uint32_t)(bRow + ni * 8) * 80 + bOff;
                ldsm2(fBhi[ni], bd + 2 * ARR);
                ldsm2(fBlo[ni], bd + 3 * ARR);
            }
#pragma unroll
            for (int mi = 0; mi < 4; mi++) {
                uint32_t fAhi[4], fAlo[4];
                uint32_t ad = stage + (uint32_t)(aRow + mi * 16) * 80 + aOff;
                ldsm4(fAhi, ad + 0 * ARR);
                ldsm4(fAlo, ad + 1 * ARR);
#pragma unroll
                for (int ni = 0; ni < 4; ni++) {
                    mma16816(acc[mi][ni], fAhi, fBhi[ni]);
                    mma16816(acc[mi][ni], fAhi, fBlo[ni]);
                    mma16816(acc[mi][ni], fAlo, fBhi[ni]);
                }
            }
        }
        __syncthreads();
    }

    // epilogue: bias + optional elu+1, write fp32
#pragma unroll
    for (int mi = 0; mi < 4; mi++) {
        int r0 = rowBase + warpM + mi * 16 + (lid >> 2);
#pragma unroll
        for (int ni = 0; ni < 4; ni++) {
            int col = colBase + warpN + ni * 8 + (lid & 3) * 2;
            float2 b2 = *(const float2*)(bias + col);
            float v0 = acc[mi][ni][0] + b2.x;
            float v1 = acc[mi][ni][1] + b2.y;
            float v2 = acc[mi][ni][2] + b2.x;
            float v3 = acc[mi][ni][3] + b2.y;
            if (act) {
                v0 = (v0 > 0.f) ? (v0 + 1.f) : expf(v0);
                v1 = (v1 > 0.f) ? (v1 + 1.f) : expf(v1);
                v2 = (v2 > 0.f) ? (v2 + 1.f) : expf(v2);
                v3 = (v3 > 0.f) ? (v3 + 1.f) : expf(v3);
            }
            float2 o0; o0.x = v0; o0.y = v1;
            float2 o1; o1.x = v2; o1.y = v3;
            *(float2*)(C + (size_t)r0 * DM + col) = o0;
            *(float2*)(C + (size_t)(r0 + 8) * DM + col) = o1;
        }
    }
}

// ---------------------------------------------------------------------------
// Attention kernels
// ---------------------------------------------------------------------------
__global__ void __launch_bounds__(256) chunk_sums_kernel()
{
    const int c = blockIdx.x;
    const int nh = blockIdx.y;
    const int n = nh >> 4;
    const int h = nh & 15;
    const int tid = threadIdx.x;

    __shared__ float Ks[64][68];
    __shared__ float Vs[64][68];

    const size_t rowbase = ((size_t)(n * LSEQ + c * CH)) * DM + h * HD;

#pragma unroll
    for (int rep = 0; rep < 4; rep++) {
        int idx = rep * 256 + tid;
        int i  = idx >> 4;
        int j4 = (idx & 15) * 4;
        *(float4*)&Ks[i][j4] = *(const float4*)(g_kp + rowbase + (size_t)i * DM + j4);
        *(float4*)&Vs[i][j4] = *(const float4*)(g_v  + rowbase + (size_t)i * DM + j4);
    }
    __syncthreads();

    const int td = (tid >> 4) * 4;
    const int tk = (tid & 15) * 4;
    float acc[4][4];
#pragma unroll
    for (int a = 0; a < 4; a++)
#pragma unroll
        for (int b = 0; b < 4; b++) acc[a][b] = 0.f;

    for (int i = 0; i < 64; i++) {
        float ka[4];
        ka[0] = Ks[i][td + 0]; ka[1] = Ks[i][td + 1];
        ka[2] = Ks[i][td + 2]; ka[3] = Ks[i][td + 3];
        float4 vv = *(const float4*)&Vs[i][tk];
        float vb[4] = {vv.x, vv.y, vv.z, vv.w};
#pragma unroll
        for (int a = 0; a < 4; a++)
#pragma unroll
            for (int b = 0; b < 4; b++)
                acc[a][b] = fmaf(ka[a], vb[b], acc[a][b]);
    }

    float* Sp = g_S + ((size_t)nh * NC + c) * (HD * HD);
#pragma unroll
    for (int a = 0; a < 4; a++) {
        float4 o; o.x=acc[a][0]; o.y=acc[a][1]; o.z=acc[a][2]; o.w=acc[a][3];
        *(float4*)&Sp[(td + a) * HD + tk] = o;
    }

    if (tid < 64) {
        float s = 0.f;
        for (int i = 0; i < 64; i++)
            s += g_qp[rowbase + (size_t)i * DM + tid];
        g_qs[((size_t)nh * NC + c) * HD + tid] = s;
    }
}

__global__ void __launch_bounds__(256) prefix_kernel()
{
    const int nh = blockIdx.x;
    const int tid = threadIdx.x;

    float run[16];
#pragma unroll
    for (int e = 0; e < 16; e++) run[e] = 0.f;

    for (int c = 0; c < NC; c++) {
        float* Sp = g_S + ((size_t)nh * NC + c) * (HD * HD);
#pragma unroll
        for (int e = 0; e < 16; e++) {
            int idx = e * 256 + tid;
            float t = Sp[idx];
            Sp[idx] = run[e];
            run[e] += t;
        }
    }

    if (tid < 64) {
        float r = 0.f;
        for (int c = 0; c < NC; c++) {
            float* qp = g_qs + ((size_t)nh * NC + c) * HD + tid;
            float t = *qp;
            *qp = r;
            r += t;
        }
    }
}

// chunk_out: O = (tril(Qp Kp^T) V + Qp P) / Z, written as bf16 split (hi,lo)
// directly into g_Ahi/g_Alo for the Wo GEMM.
#define TS (64 * 68)
__global__ void __launch_bounds__(256) chunk_out_kernel()
{
    extern __shared__ float fsm[];
    float* Qs = fsm;
    float* Kt = fsm + TS;
    float* Vs = fsm + 2 * TS;
    float* Ps = fsm + 3 * TS;
    float* As = fsm + 4 * TS;

    const int c = blockIdx.x;
    const int nh = blockIdx.y;
    const int n = nh >> 4;
    const int h = nh & 15;
    const int tid = threadIdx.x;

    const size_t rowbase = ((size_t)(n * LSEQ + c * CH)) * DM + h * HD;
    const float* Sp = g_S + ((size_t)nh * NC + c) * (HD * HD);

#pragma unroll
    for (int rep = 0; rep < 4; rep++) {
        int idx = rep * 256 + tid;
        int i  = idx >> 4;
        int j4 = (idx & 15) * 4;
        float4 q = *(const float4*)(g_qp + rowbase + (size_t)i * DM + j4);
        *(float4*)&Qs[i * 68 + j4] = q;
        float4 k = *(const float4*)(g_kp + rowbase + (size_t)i * DM + j4);
        Kt[(j4 + 0) * 68 + i] = k.x;
        Kt[(j4 + 1) * 68 + i] = k.y;
        Kt[(j4 + 2) * 68 + i] = k.z;
        Kt[(j4 + 3) * 68 + i] = k.w;
        float4 v = *(const float4*)(g_v + rowbase + (size_t)i * DM + j4);
        *(float4*)&Vs[i * 68 + j4] = v;
        float4 p = *(const float4*)(Sp + idx * 4);
        int d = (idx * 4) >> 6;
        int kk = (idx * 4) & 63;
        *(float4*)&Ps[d * 68 + kk] = p;
    }
    __syncthreads();

    const int ti = (tid >> 4) * 4;
    const int tj = (tid & 15) * 4;

    {
        float acc[4][4];
#pragma unroll
        for (int a = 0; a < 4; a++)
#pragma unroll
            for (int b = 0; b < 4; b++) acc[a][b] = 0.f;
        for (int d = 0; d < 64; d++) {
            float qa[4];
            qa[0] = Qs[(ti + 0) * 68 + d]; qa[1] = Qs[(ti + 1) * 68 + d];
            qa[2] = Qs[(ti + 2) * 68 + d]; qa[3] = Qs[(ti + 3) * 68 + d];
            float4 kb = *(const float4*)&Kt[d * 68 + tj];
            float kv[4] = {kb.x, kb.y, kb.z, kb.w};
#pragma unroll
            for (int a = 0; a < 4; a++)
#pragma unroll
                for (int b = 0; b < 4; b++)
                    acc[a][b] = fmaf(qa[a], kv[b], acc[a][b]);
        }
#pragma unroll
        for (int a = 0; a < 4; a++) {
            float4 o;
            o.x = (tj + 0 <= ti + a) ? acc[a][0] : 0.f;
            o.y = (tj + 1 <= ti + a) ? acc[a][1] : 0.f;
            o.z = (tj + 2 <= ti + a) ? acc[a][2] : 0.f;
            o.w = (tj + 3 <= ti + a) ? acc[a][3] : 0.f;
            *(float4*)&As[(ti + a) * 68 + tj] = o;
        }
    }
    __syncthreads();

    float* Zc = Kt;
    if (tid < 64) {
        float z = g_qs[((size_t)nh * NC + c) * HD + tid];
        for (int i = 0; i < 64; i++) {
            z += Qs[i * 68 + tid];
            Zc[i * 68 + tid] = z;
        }
    }
    __syncthreads();

    {
        const int tk = tj;
        float acc[4][4];
#pragma unroll
        for (int a = 0; a < 4; a++)
#pragma unroll
            for (int b = 0; b < 4; b++) acc[a][b] = 0.f;

        for (int j = 0; j < 64; j++) {
            float aa[4];
            aa[0] = As[(ti + 0) * 68 + j]; aa[1] = As[(ti + 1) * 68 + j];
            aa[2] = As[(ti + 2) * 68 + j]; aa[3] = As[(ti + 3) * 68 + j];
            float4 vv = *(const float4*)&Vs[j * 68 + tk];
            float vb[4] = {vv.x, vv.y, vv.z, vv.w};
#pragma unroll
            for (int a = 0; a < 4; a++)
#pragma unroll
                for (int b = 0; b < 4; b++)
                    acc[a][b] = fmaf(aa[a], vb[b], acc[a][b]);
        }
        for (int d = 0; d < 64; d++) {
            float qa[4];
            qa[0] = Qs[(ti + 0) * 68 + d]; qa[1] = Qs[(ti + 1) * 68 + d];
            qa[2] = Qs[(ti + 2) * 68 + d]; qa[3] = Qs[(ti + 3) * 68 + d];
            float4 pp = *(const float4*)&Ps[d * 68 + tk];
            float pb[4] = {pp.x, pp.y, pp.z, pp.w};
#pragma unroll
            for (int a = 0; a < 4; a++)
#pragma unroll
                for (int b = 0; b < 4; b++)
                    acc[a][b] = fmaf(qa[a], pb[b], acc[a][b]);
        }

#pragma unroll
        for (int a = 0; a < 4; a++) {
            float4 z4 = *(const float4*)&Zc[(ti + a) * 68 + tk];
            float o[4];
            o[0] = acc[a][0] / z4.x;
            o[1] = acc[a][1] / z4.y;
            o[2] = acc[a][2] / z4.z;
            o[3] = acc[a][3] / z4.w;
            // write bf16 split directly (att hi/lo)
            __nv_bfloat16 h0 = __float2bfloat16(o[0]);
            __nv_bfloat16 h1 = __float2bfloat16(o[1]);
            __nv_bfloat16 h2 = __float2bfloat16(o[2]);
            __nv_bfloat16 h3 = __float2bfloat16(o[3]);
            __nv_bfloat16 l0 = __float2bfloat16(o[0] - __bfloat162float(h0));
            __nv_bfloat16 l1 = __float2bfloat16(o[1] - __bfloat162float(h1));
            __nv_bfloat16 l2 = __float2bfloat16(o[2] - __bfloat162float(h2));
            __nv_bfloat16 l3 = __float2bfloat16(o[3] - __bfloat162float(h3));
            size_t eo = rowbase + (size_t)(ti + a) * DM + tk;
            *(__nv_bfloat162*)(g_Ahi + eo)     = __nv_bfloat162(h0, h1);
            *(__nv_bfloat162*)(g_Ahi + eo + 2) = __nv_bfloat162(h2, h3);
            *(__nv_bfloat162*)(g_Alo + eo)     = __nv_bfloat162(l0, l1);
            *(__nv_bfloat162*)(g_Alo + eo + 2) = __nv_bfloat162(l2, l3);
        }
    }
}

// ---------------------------------------------------------------------------
extern "C" void kernel_launch(void* const* d_in, const int* in_sizes, int n_in,
                              void* d_out, int out_size)
{
    const float* queries = (const float*)d_in[0];
    const float* keys    = (const float*)d_in[1];
    const float* values  = (const float*)d_in[2];
    const float* Wq = (const float*)d_in[3];
    const float* bq = (const float*)d_in[4];
    const float* Wk = (const float*)d_in[5];
    const float* bk = (const float*)d_in[6];
    const float* Wv = (const float*)d_in[7];
    const float* bv = (const float*)d_in[8];
    const float* Wo = (const float*)d_in[9];
    const float* bo = (const float*)d_in[10];
    float* out = (float*)d_out;

    float* qp;  cudaGetSymbolAddress((void**)&qp,  g_qp);
    float* kp;  cudaGetSymbolAddress((void**)&kp,  g_kp);
    float* vv;  cudaGetSymbolAddress((void**)&vv,  g_v);
    __nv_bfloat16* ahi; cudaGetSymbolAddress((void**)&ahi, g_Ahi);
    __nv_bfloat16* alo; cudaGetSymbolAddress((void**)&alo, g_Alo);
    __nv_bfloat16* whi; cudaGetSymbolAddress((void**)&whi, g_Whi);
    __nv_bfloat16* wlo; cudaGetSymbolAddress((void**)&wlo, g_Wlo);

    static bool attrSet = false;
    if (!attrSet) {
        cudaFuncSetAttribute(gemm_mma, cudaFuncAttributeMaxDynamicSharedMemorySize,
                             GEMM_SMEM);
        cudaFuncSetAttribute(chunk_out_kernel,
                             cudaFuncAttributeMaxDynamicSharedMemorySize,
                             (int)(5 * TS * sizeof(float)));
        attrSet = true;
    }

    const int splitBlocks = (MROWS * DM / 4 + 255) / 256;
    dim3 tsGrid(DM / 32, DM / 32);
    dim3 gemmGrid(DM / 128, MROWS / 128);

    // Q projection
    transpose_split<<<tsGrid, 256>>>(Wq, whi, wlo);
    split_input<<<splitBlocks, 256>>>(queries, ahi, alo, MROWS * DM / 4);
    gemm_mma<<<gemmGrid, 256, GEMM_SMEM>>>(ahi, alo, whi, wlo, bq, qp, 1);

    // K projection
    transpose_split<<<tsGrid, 256>>>(Wk, whi, wlo);
    split_input<<<splitBlocks, 256>>>(keys, ahi, alo, MROWS * DM / 4);
    gemm_mma<<<gemmGrid, 256, GEMM_SMEM>>>(ahi, alo, whi, wlo, bk, kp, 1);

    // V projection
    transpose_split<<<tsGrid, 256>>>(Wv, whi, wlo);
    split_input<<<splitBlocks, 256>>>(values, ahi, alo, MROWS * DM / 4);
    gemm_mma<<<gemmGrid, 256, GEMM_SMEM>>>(ahi, alo, whi, wlo, bv, vv, 0);

    // Chunked causal linear attention (chunk_out writes att hi/lo directly)
    dim3 chunkGrid(NC, NH);
    chunk_sums_kernel<<<chunkGrid, 256>>>();
    prefix_kernel<<<NH, 256>>>();
    chunk_out_kernel<<<chunkGrid, 256, 5 * TS * sizeof(float)>>>();

    // Output projection (att already split by chunk_out)
    transpose_split<<<tsGrid, 256>>>(Wo, whi, wlo);
    gemm_mma<<<gemmGrid, 256, GEMM_SMEM>>>(ahi, alo, whi, wlo, bo, out, 0);
}

// round 5
// speedup vs baseline: 2.5580x; 1.3348x over previous
#include <cuda_runtime.h>
#include <cuda_fp16.h>
#include <math.h>
#include <cstdint>

// Problem constants
#define NB 4
#define LSEQ 2048
#define DM 1024
#define NHEAD 16
#define HD 64
#define MROWS (NB * LSEQ)   // 8192
#define CH 64
#define NC (LSEQ / CH)      // 32
#define NH (NB * NHEAD)     // 64

// Scratch (device globals; no allocation allowed)
__device__ float g_qp[MROWS * DM];
__device__ float g_kp[MROWS * DM];
__device__ float g_v [MROWS * DM];
__device__ float g_S [NH * NC * HD * HD];
__device__ float g_qs[NH * NC * HD];

// fp16 GEMM operand scratch
__device__ __half g_Ah [3 * MROWS * DM];   // q,k,v inputs (and att reuses slot 0)
__device__ __half g_Whi[3 * DM * DM];      // transposed [n][k]
__device__ __half g_Wlo[3 * DM * DM];

// ---------------------------------------------------------------------------
// PTX helpers
// ---------------------------------------------------------------------------
__device__ __forceinline__ uint32_t smem_u32(const void* p) {
    uint32_t a;
    asm("{ .reg .u64 t; cvta.to.shared.u64 t, %1; cvt.u32.u64 %0, t; }"
        : "=r"(a) : "l"(p));
    return a;
}

#define CPASYNC16(s, g) \
    asm volatile("cp.async.cg.shared.global [%0], [%1], 16;" \
                 :: "r"(s), "l"(g) : "memory")
#define CPCOMMIT() asm volatile("cp.async.commit_group;" ::: "memory")
#define CPWAIT1()  asm volatile("cp.async.wait_group 1;" ::: "memory")
#define CPWAIT0()  asm volatile("cp.async.wait_group 0;" ::: "memory")

__device__ __forceinline__ void ldsm4(uint32_t* r, uint32_t a) {
    asm volatile("ldmatrix.sync.aligned.m8n8.x4.shared.b16 {%0,%1,%2,%3}, [%4];"
        : "=r"(r[0]), "=r"(r[1]), "=r"(r[2]), "=r"(r[3]) : "r"(a));
}
__device__ __forceinline__ void ldsm2(uint32_t* r, uint32_t a) {
    asm volatile("ldmatrix.sync.aligned.m8n8.x2.shared.b16 {%0,%1}, [%2];"
        : "=r"(r[0]), "=r"(r[1]) : "r"(a));
}
__device__ __forceinline__ void mma16816(float* c, const uint32_t* a, const uint32_t* b) {
    asm volatile("mma.sync.aligned.m16n8k16.row.col.f32.f16.f16.f32 "
        "{%0,%1,%2,%3}, {%4,%5,%6,%7}, {%8,%9}, {%0,%1,%2,%3};"
        : "+f"(c[0]), "+f"(c[1]), "+f"(c[2]), "+f"(c[3])
        : "r"(a[0]), "r"(a[1]), "r"(a[2]), "r"(a[3]), "r"(b[0]), "r"(b[1]));
}

// ---------------------------------------------------------------------------
// split_input3: fp32 -> fp16 (hi only), batched over z = {q,k,v}
// ---------------------------------------------------------------------------
__global__ void __launch_bounds__(256) split_input3(
    const float* __restrict__ Xq, const float* __restrict__ Xk,
    const float* __restrict__ Xv, int n4)
{
    int z = blockIdx.y;
    const float* X = (z == 0) ? Xq : (z == 1) ? Xk : Xv;
    __half* out = g_Ah + (size_t)z * MROWS * DM;
    int idx = blockIdx.x * 256 + threadIdx.x;
    if (idx >= n4) return;
    float4 x = ((const float4*)X)[idx];
    __half2 h01 = __floats2half2_rn(x.x, x.y);
    __half2 h23 = __floats2half2_rn(x.z, x.w);
    __half2* op = (__half2*)out;
    op[idx * 2 + 0] = h01;
    op[idx * 2 + 1] = h23;
}

// transpose_split3: W[k][n] fp32 -> Wt hi/lo fp16 [n][k], batched over z
__global__ void __launch_bounds__(256) transpose_split3(
    const float* __restrict__ W0, const float* __restrict__ W1,
    const float* __restrict__ W2)
{
    __shared__ float t[32][33];
    int z = blockIdx.z;
    const float* W = (z == 0) ? W0 : (z == 1) ? W1 : W2;
    __half* hi = g_Whi + (size_t)z * DM * DM;
    __half* lo = g_Wlo + (size_t)z * DM * DM;
    int bx = blockIdx.x * 32;   // n base
    int by = blockIdx.y * 32;   // k base
    int tx = threadIdx.x & 31;
    int ty = threadIdx.x >> 5;  // 0..7
#pragma unroll
    for (int i = 0; i < 4; i++) {
        int k = by + ty + i * 8;
        t[ty + i * 8][tx] = W[(size_t)k * DM + bx + tx];
    }
    __syncthreads();
#pragma unroll
    for (int i = 0; i < 4; i++) {
        int n = bx + ty + i * 8;
        int k = by + tx;
        float v = t[tx][ty + i * 8];
        __half h = __float2half_rn(v);
        __half l = __float2half_rn(v - __half2float(h));
        hi[(size_t)n * DM + k] = h;
        lo[(size_t)n * DM + k] = l;
    }
}

// ---------------------------------------------------------------------------
// fp16 2-term GEMM: C = Ahi @ (Whi + Wlo) + bias (+elu+1)
// BM=BN=128, BK=32, 256 threads, warp tile 64x32, cp.async 2-stage, 2 CTA/SM.
// 3 smem arrays (A, Whi, Wlo), 80B-padded rows. grid.z batches projections.
// ---------------------------------------------------------------------------
#define ARR 10240            // 128 rows * 80B
#define STG (3 * ARR)        // 30720 per stage
#define GEMM_SMEM (2 * STG)  // 61440

__device__ __forceinline__ void load_stage(
    uint32_t sbase, int tid, int k0,
    const __half* pA, const __half* pWhi, const __half* pWlo)
{
#pragma unroll
    for (int rep = 0; rep < 2; rep++) {
        int l = rep * 256 + tid;        // 0..511
        int row = l >> 2;               // 0..127
        int ch = l & 3;                 // 0..3 (16B chunks)
        uint32_t so = sbase + (uint32_t)row * 80 + ch * 16;
        size_t go = (size_t)row * DM + k0 + ch * 8;
        CPASYNC16(so + 0 * ARR, pA + go);
        CPASYNC16(so + 1 * ARR, pWhi + go);
        CPASYNC16(so + 2 * ARR, pWlo + go);
    }
}

__global__ void __launch_bounds__(256, 2) gemm_f16(
    const __half* __restrict__ Ah,
    const __half* __restrict__ Whi, const __half* __restrict__ Wlo,
    const float* __restrict__ b0, const float* __restrict__ b1,
    const float* __restrict__ b2,
    float* __restrict__ C0, float* __restrict__ C1, float* __restrict__ C2,
    int actMask)
{
    extern __shared__ char smem[];
    const uint32_t sb = smem_u32(smem);
    const int z = blockIdx.z;
    const int tid = threadIdx.x;
    const int wid = tid >> 5;
    const int lid = tid & 31;
    const int rowBase = blockIdx.y * 128;
    const int colBase = blockIdx.x * 128;
    const int warpM = (wid >> 2) * 64;
    const int warpN = (wid & 3) * 32;

    const float* bias = (z == 0) ? b0 : (z == 1) ? b1 : b2;
    float* C = (z == 0) ? C0 : (z == 1) ? C1 : C2;
    const int act = (actMask >> z) & 1;

    const __half* pA   = Ah  + (size_t)z * MROWS * DM + (size_t)rowBase * DM;
    const __half* pWhi = Whi + (size_t)z * DM * DM + (size_t)colBase * DM;
    const __half* pWlo = Wlo + (size_t)z * DM * DM + (size_t)colBase * DM;

    float acc[4][4][4];
#pragma unroll
    for (int i = 0; i < 4; i++)
#pragma unroll
        for (int j = 0; j < 4; j++)
#pragma unroll
            for (int e = 0; e < 4; e++) acc[i][j][e] = 0.f;

    load_stage(sb, tid, 0, pA, pWhi, pWlo);
    CPCOMMIT();

    const int aRow = warpM + (lid & 15);
    const uint32_t aCol = ((lid >> 4) & 1) * 16;
    const int bRow = warpN + (lid & 7);
    const uint32_t bCol = ((lid >> 3) & 1) * 16;

    for (int c = 0; c < 32; c++) {
        if (c + 1 < 32) {
            load_stage(sb + ((c + 1) & 1) * STG, tid, (c + 1) * 32,
                       pA, pWhi, pWlo);
            CPCOMMIT();
            CPWAIT1();
        } else {
            CPWAIT0();
        }
        __syncthreads();

        const uint32_t stage = sb + (c & 1) * STG;
#pragma unroll
        for (int kk = 0; kk < 2; kk++) {
            const uint32_t aOff = (uint32_t)kk * 32 + aCol;
            const uint32_t bOff = (uint32_t)kk * 32 + bCol;
            uint32_t fBhi[4][2], fBlo[4][2];
#pragma unroll
            for (int ni = 0; ni < 4; ni++) {
                uint32_t bd = stage + (uint32_t)(bRow + ni * 8) * 80 + bOff;
                ldsm2(fBhi[ni], bd + 1 * ARR);
                ldsm2(fBlo[ni], bd + 2 * ARR);
            }
#pragma unroll
            for (int mi = 0; mi < 4; mi++) {
                uint32_t fA[4];
                ldsm4(fA, stage + (uint32_t)(aRow + mi * 16) * 80 + aOff);
#pragma unroll
                for (int ni = 0; ni < 4; ni++) {
                    mma16816(acc[mi][ni], fA, fBhi[ni]);
                    mma16816(acc[mi][ni], fA, fBlo[ni]);
                }
            }
        }
        __syncthreads();
    }

    // epilogue: bias + optional elu+1, write fp32
#pragma unroll
    for (int mi = 0; mi < 4; mi++) {
        int r0 = rowBase + warpM + mi * 16 + (lid >> 2);
#pragma unroll
        for (int ni = 0; ni < 4; ni++) {
            int col = colBase + warpN + ni * 8 + (lid & 3) * 2;
            float2 b2v = *(const float2*)(bias + col);
            float v0 = acc[mi][ni][0] + b2v.x;
            float v1 = acc[mi][ni][1] + b2v.y;
            float v2 = acc[mi][ni][2] + b2v.x;
            float v3 = acc[mi][ni][3] + b2v.y;
            if (act) {
                v0 = (v0 > 0.f) ? (v0 + 1.f) : expf(v0);
                v1 = (v1 > 0.f) ? (v1 + 1.f) : expf(v1);
                v2 = (v2 > 0.f) ? (v2 + 1.f) : expf(v2);
                v3 = (v3 > 0.f) ? (v3 + 1.f) : expf(v3);
            }
            float2 o0; o0.x = v0; o0.y = v1;
            float2 o1; o1.x = v2; o1.y = v3;
            *(float2*)(C + (size_t)r0 * DM + col) = o0;
            *(float2*)(C + (size_t)(r0 + 8) * DM + col) = o1;
        }
    }
}

// ---------------------------------------------------------------------------
// Attention kernels
// ---------------------------------------------------------------------------
__global__ void __launch_bounds__(256) chunk_sums_kernel()
{
    const int c = blockIdx.x;
    const int nh = blockIdx.y;
    const int n = nh >> 4;
    const int h = nh & 15;
    const int tid = threadIdx.x;

    __shared__ float Ks[64][68];
    __shared__ float Vs[64][68];

    const size_t rowbase = ((size_t)(n * LSEQ + c * CH)) * DM + h * HD;

#pragma unroll
    for (int rep = 0; rep < 4; rep++) {
        int idx = rep * 256 + tid;
        int i  = idx >> 4;
        int j4 = (idx & 15) * 4;
        *(float4*)&Ks[i][j4] = *(const float4*)(g_kp + rowbase + (size_t)i * DM + j4);
        *(float4*)&Vs[i][j4] = *(const float4*)(g_v  + rowbase + (size_t)i * DM + j4);
    }
    __syncthreads();

    const int td = (tid >> 4) * 4;
    const int tk = (tid & 15) * 4;
    float acc[4][4];
#pragma unroll
    for (int a = 0; a < 4; a++)
#pragma unroll
        for (int b = 0; b < 4; b++) acc[a][b] = 0.f;

    for (int i = 0; i < 64; i++) {
        float ka[4];
        ka[0] = Ks[i][td + 0]; ka[1] = Ks[i][td + 1];
        ka[2] = Ks[i][td + 2]; ka[3] = Ks[i][td + 3];
        float4 vv = *(const float4*)&Vs[i][tk];
        float vb[4] = {vv.x, vv.y, vv.z, vv.w};
#pragma unroll
        for (int a = 0; a < 4; a++)
#pragma unroll
            for (int b = 0; b < 4; b++)
                acc[a][b] = fmaf(ka[a], vb[b], acc[a][b]);
    }

    float* Sp = g_S + ((size_t)nh * NC + c) * (HD * HD);
#pragma unroll
    for (int a = 0; a < 4; a++) {
        float4 o; o.x=acc[a][0]; o.y=acc[a][1]; o.z=acc[a][2]; o.w=acc[a][3];
        *(float4*)&Sp[(td + a) * HD + tk] = o;
    }

    if (tid < 64) {
        float s = 0.f;
        for (int i = 0; i < 64; i++)
            s += g_qp[rowbase + (size_t)i * DM + tid];
        g_qs[((size_t)nh * NC + c) * HD + tid] = s;
    }
}

__global__ void __launch_bounds__(256) prefix_kernel()
{
    const int nh = blockIdx.x;
    const int tid = threadIdx.x;

    float run[16];
#pragma unroll
    for (int e = 0; e < 16; e++) run[e] = 0.f;

    for (int c = 0; c < NC; c++) {
        float* Sp = g_S + ((size_t)nh * NC + c) * (HD * HD);
#pragma unroll
        for (int e = 0; e < 16; e++) {
            int idx = e * 256 + tid;
            float t = Sp[idx];
            Sp[idx] = run[e];
            run[e] += t;
        }
    }

    if (tid < 64) {
        float r = 0.f;
        for (int c = 0; c < NC; c++) {
            float* qp = g_qs + ((size_t)nh * NC + c) * HD + tid;
            float t = *qp;
            *qp = r;
            r += t;
        }
    }
}

// chunk_out: O = (tril(Qp Kp^T) V + Qp P) / Z, written as fp16 into g_Ah[0]
#define TS (64 * 68)
__global__ void __launch_bounds__(256) chunk_out_kernel()
{
    extern __shared__ float fsm[];
    float* Qs = fsm;
    float* Kt = fsm + TS;
    float* Vs = fsm + 2 * TS;
    float* Ps = fsm + 3 * TS;
    float* As = fsm + 4 * TS;

    const int c = blockIdx.x;
    const int nh = blockIdx.y;
    const int n = nh >> 4;
    const int h = nh & 15;
    const int tid = threadIdx.x;

    const size_t rowbase = ((size_t)(n * LSEQ + c * CH)) * DM + h * HD;
    const float* Sp = g_S + ((size_t)nh * NC + c) * (HD * HD);

#pragma unroll
    for (int rep = 0; rep < 4; rep++) {
        int idx = rep * 256 + tid;
        int i  = idx >> 4;
        int j4 = (idx & 15) * 4;
        float4 q = *(const float4*)(g_qp + rowbase + (size_t)i * DM + j4);
        *(float4*)&Qs[i * 68 + j4] = q;
        float4 k = *(const float4*)(g_kp + rowbase + (size_t)i * DM + j4);
        Kt[(j4 + 0) * 68 + i] = k.x;
        Kt[(j4 + 1) * 68 + i] = k.y;
        Kt[(j4 + 2) * 68 + i] = k.z;
        Kt[(j4 + 3) * 68 + i] = k.w;
        float4 v = *(const float4*)(g_v + rowbase + (size_t)i * DM + j4);
        *(float4*)&Vs[i * 68 + j4] = v;
        float4 p = *(const float4*)(Sp + idx * 4);
        int d = (idx * 4) >> 6;
        int kk = (idx * 4) & 63;
        *(float4*)&Ps[d * 68 + kk] = p;
    }
    __syncthreads();

    const int ti = (tid >> 4) * 4;
    const int tj = (tid & 15) * 4;

    {
        float acc[4][4];
#pragma unroll
        for (int a = 0; a < 4; a++)
#pragma unroll
            for (int b = 0; b < 4; b++) acc[a][b] = 0.f;
        for (int d = 0; d < 64; d++) {
            float qa[4];
            qa[0] = Qs[(ti + 0) * 68 + d]; qa[1] = Qs[(ti + 1) * 68 + d];
            qa[2] = Qs[(ti + 2) * 68 + d]; qa[3] = Qs[(ti + 3) * 68 + d];
            float4 kb = *(const float4*)&Kt[d * 68 + tj];
            float kv[4] = {kb.x, kb.y, kb.z, kb.w};
#pragma unroll
            for (int a = 0; a < 4; a++)
#pragma unroll
                for (int b = 0; b < 4; b++)
                    acc[a][b] = fmaf(qa[a], kv[b], acc[a][b]);
        }
#pragma unroll
        for (int a = 0; a < 4; a++) {
            float4 o;
            o.x = (tj + 0 <= ti + a) ? acc[a][0] : 0.f;
            o.y = (tj + 1 <= ti + a) ? acc[a][1] : 0.f;
            o.z = (tj + 2 <= ti + a) ? acc[a][2] : 0.f;
            o.w = (tj + 3 <= ti + a) ? acc[a][3] : 0.f;
            *(float4*)&As[(ti + a) * 68 + tj] = o;
        }
    }
    __syncthreads();

    float* Zc = Kt;
    if (tid < 64) {
        float z = g_qs[((size_t)nh * NC + c) * HD + tid];
        for (int i = 0; i < 64; i++) {
            z += Qs[i * 68 + tid];
            Zc[i * 68 + tid] = z;
        }
    }
    __syncthreads();

    {
        const int tk = tj;
        float acc[4][4];
#pragma unroll
        for (int a = 0; a < 4; a++)
#pragma unroll
            for (int b = 0; b < 4; b++) acc[a][b] = 0.f;

        for (int j = 0; j < 64; j++) {
            float aa[4];
            aa[0] = As[(ti + 0) * 68 + j]; aa[1] = As[(ti + 1) * 68 + j];
            aa[2] = As[(ti + 2) * 68 + j]; aa[3] = As[(ti + 3) * 68 + j];
            float4 vv = *(const float4*)&Vs[j * 68 + tk];
            float vb[4] = {vv.x, vv.y, vv.z, vv.w};
#pragma unroll
            for (int a = 0; a < 4; a++)
#pragma unroll
                for (int b = 0; b < 4; b++)
                    acc[a][b] = fmaf(aa[a], vb[b], acc[a][b]);
        }
        for (int d = 0; d < 64; d++) {
            float qa[4];
            qa[0] = Qs[(ti + 0) * 68 + d]; qa[1] = Qs[(ti + 1) * 68 + d];
            qa[2] = Qs[(ti + 2) * 68 + d]; qa[3] = Qs[(ti + 3) * 68 + d];
            float4 pp = *(const float4*)&Ps[d * 68 + tk];
            float pb[4] = {pp.x, pp.y, pp.z, pp.w};
#pragma unroll
            for (int a = 0; a < 4; a++)
#pragma unroll
                for (int b = 0; b < 4; b++)
                    acc[a][b] = fmaf(qa[a], pb[b], acc[a][b]);
        }

#pragma unroll
        for (int a = 0; a < 4; a++) {
            float4 z4 = *(const float4*)&Zc[(ti + a) * 68 + tk];
            __half2 h01 = __floats2half2_rn(acc[a][0] / z4.x, acc[a][1] / z4.y);
            __half2 h23 = __floats2half2_rn(acc[a][2] / z4.z, acc[a][3] / z4.w);
            size_t eo = rowbase + (size_t)(ti + a) * DM + tk;
            *(__half2*)(g_Ah + eo)     = h01;
            *(__half2*)(g_Ah + eo + 2) = h23;
        }
    }
}

// ---------------------------------------------------------------------------
extern "C" void kernel_launch(void* const* d_in, const int* in_sizes, int n_in,
                              void* d_out, int out_size)
{
    const float* queries = (const float*)d_in[0];
    const float* keys    = (const float*)d_in[1];
    const float* values  = (const float*)d_in[2];
    const float* Wq = (const float*)d_in[3];
    const float* bq = (const float*)d_in[4];
    const float* Wk = (const float*)d_in[5];
    const float* bk = (const float*)d_in[6];
    const float* Wv = (const float*)d_in[7];
    const float* bv = (const float*)d_in[8];
    const float* Wo = (const float*)d_in[9];
    const float* bo = (const float*)d_in[10];
    float* out = (float*)d_out;

    float* qp;  cudaGetSymbolAddress((void**)&qp,  g_qp);
    float* kp;  cudaGetSymbolAddress((void**)&kp,  g_kp);
    float* vv;  cudaGetSymbolAddress((void**)&vv,  g_v);
    __half* ah;  cudaGetSymbolAddress((void**)&ah,  g_Ah);
    __half* whi; cudaGetSymbolAddress((void**)&whi, g_Whi);
    __half* wlo; cudaGetSymbolAddress((void**)&wlo, g_Wlo);

    static bool attrSet = false;
    if (!attrSet) {
        cudaFuncSetAttribute(gemm_f16, cudaFuncAttributeMaxDynamicSharedMemorySize,
                             GEMM_SMEM);
        cudaFuncSetAttribute(chunk_out_kernel,
                             cudaFuncAttributeMaxDynamicSharedMemorySize,
                             (int)(5 * TS * sizeof(float)));
        attrSet = true;
    }

    const int splitBlocks = (MROWS * DM / 4 + 255) / 256;

    // Split inputs (q,k,v) and weights (Wq,Wk,Wv) — batched
    split_input3<<<dim3(splitBlocks, 3), 256>>>(queries, keys, values,
                                                MROWS * DM / 4);
    transpose_split3<<<dim3(DM / 32, DM / 32, 3), 256>>>(Wq, Wk, Wv);

    // Fused Q/K/V projections (one launch, grid.z = 3)
    gemm_f16<<<dim3(DM / 128, MROWS / 128, 3), 256, GEMM_SMEM>>>(
        ah, whi, wlo, bq, bk, bv, qp, kp, vv, 0x3);

    // Chunked causal linear attention (chunk_out writes fp16 att into slot 0)
    dim3 chunkGrid(NC, NH);
    chunk_sums_kernel<<<chunkGrid, 256>>>();
    prefix_kernel<<<NH, 256>>>();
    chunk_out_kernel<<<chunkGrid, 256, 5 * TS * sizeof(float)>>>();

    // Output projection: att (slot 0 of g_Ah) @ Wo + bo
    transpose_split3<<<dim3(DM / 32, DM / 32, 1), 256>>>(Wo, Wo, Wo);
    gemm_f16<<<dim3(DM / 128, MROWS / 128, 1), 256, GEMM_SMEM>>>(
        ah, whi, wlo, bo, bo, bo, out, out, out, 0x0);
}

// round 6
// speedup vs baseline: 2.9659x; 1.1594x over previous
#include <cuda_runtime.h>
#include <cuda_fp16.h>
#include <math.h>
#include <cstdint>

// Problem constants
#define NB 4
#define LSEQ 2048
#define DM 1024
#define NHEAD 16
#define HD 64
#define MROWS (NB * LSEQ)   // 8192
#define CH 64
#define NC (LSEQ / CH)      // 32
#define NH (NB * NHEAD)     // 64

// Scratch (device globals; no allocation allowed)
__device__ float g_qp[MROWS * DM];          // elu(q)+1 fp32 (needed for Z)
__device__ __half g_kh[MROWS * DM];         // elu(k)+1 fp16
__device__ __half g_vh[MROWS * DM];         // v projection fp16
__device__ float g_S [NH * NC * HD * HD];
__device__ float g_qs[NH * NC * HD];

// fp16 GEMM operand scratch
__device__ __half g_Ah [3 * MROWS * DM];    // q,k,v inputs (att reuses slot 0)
__device__ __half g_Whi[4 * DM * DM];       // transposed [n][k]; slot 3 = Wo
__device__ __half g_Wlo[4 * DM * DM];

// ---------------------------------------------------------------------------
// PTX helpers
// ---------------------------------------------------------------------------
__device__ __forceinline__ uint32_t smem_u32(const void* p) {
    uint32_t a;
    asm("{ .reg .u64 t; cvta.to.shared.u64 t, %1; cvt.u32.u64 %0, t; }"
        : "=r"(a) : "l"(p));
    return a;
}

#define CPASYNC16(s, g) \
    asm volatile("cp.async.cg.shared.global [%0], [%1], 16;" \
                 :: "r"(s), "l"(g) : "memory")
#define CPCOMMIT() asm volatile("cp.async.commit_group;" ::: "memory")
#define CPWAIT1()  asm volatile("cp.async.wait_group 1;" ::: "memory")
#define CPWAIT0()  asm volatile("cp.async.wait_group 0;" ::: "memory")

__device__ __forceinline__ void ldsm4(uint32_t* r, uint32_t a) {
    asm volatile("ldmatrix.sync.aligned.m8n8.x4.shared.b16 {%0,%1,%2,%3}, [%4];"
        : "=r"(r[0]), "=r"(r[1]), "=r"(r[2]), "=r"(r[3]) : "r"(a));
}
__device__ __forceinline__ void ldsm2(uint32_t* r, uint32_t a) {
    asm volatile("ldmatrix.sync.aligned.m8n8.x2.shared.b16 {%0,%1}, [%2];"
        : "=r"(r[0]), "=r"(r[1]) : "r"(a));
}
__device__ __forceinline__ void mma16816(float* c, const uint32_t* a, const uint32_t* b) {
    asm volatile("mma.sync.aligned.m16n8k16.row.col.f32.f16.f16.f32 "
        "{%0,%1,%2,%3}, {%4,%5,%6,%7}, {%8,%9}, {%0,%1,%2,%3};"
        : "+f"(c[0]), "+f"(c[1]), "+f"(c[2]), "+f"(c[3])
        : "r"(a[0]), "r"(a[1]), "r"(a[2]), "r"(a[3]), "r"(b[0]), "r"(b[1]));
}

// ---------------------------------------------------------------------------
// split_input3: fp32 -> fp16, batched over z = {q,k,v}
// ---------------------------------------------------------------------------
__global__ void __launch_bounds__(256) split_input3(
    const float* __restrict__ Xq, const float* __restrict__ Xk,
    const float* __restrict__ Xv, int n4)
{
    int z = blockIdx.y;
    const float* X = (z == 0) ? Xq : (z == 1) ? Xk : Xv;
    __half* out = g_Ah + (size_t)z * MROWS * DM;
    int idx = blockIdx.x * 256 + threadIdx.x;
    if (idx >= n4) return;
    float4 x = ((const float4*)X)[idx];
    __half2* op = (__half2*)out;
    op[idx * 2 + 0] = __floats2half2_rn(x.x, x.y);
    op[idx * 2 + 1] = __floats2half2_rn(x.z, x.w);
}

// transpose_split4: W[k][n] fp32 -> Wt hi/lo fp16 [n][k], batched over 4 weights
__global__ void __launch_bounds__(256) transpose_split4(
    const float* __restrict__ W0, const float* __restrict__ W1,
    const float* __restrict__ W2, const float* __restrict__ W3)
{
    __shared__ float t[32][33];
    int z = blockIdx.z;
    const float* W = (z == 0) ? W0 : (z == 1) ? W1 : (z == 2) ? W2 : W3;
    __half* hi = g_Whi + (size_t)z * DM * DM;
    __half* lo = g_Wlo + (size_t)z * DM * DM;
    int bx = blockIdx.x * 32;   // n base
    int by = blockIdx.y * 32;   // k base
    int tx = threadIdx.x & 31;
    int ty = threadIdx.x >> 5;  // 0..7
#pragma unroll
    for (int i = 0; i < 4; i++) {
        int k = by + ty + i * 8;
        t[ty + i * 8][tx] = W[(size_t)k * DM + bx + tx];
    }
    __syncthreads();
#pragma unroll
    for (int i = 0; i < 4; i++) {
        int n = bx + ty + i * 8;
        int k = by + tx;
        float v = t[tx][ty + i * 8];
        __half h = __float2half_rn(v);
        __half l = __float2half_rn(v - __half2float(h));
        hi[(size_t)n * DM + k] = h;
        lo[(size_t)n * DM + k] = l;
    }
}

// ---------------------------------------------------------------------------
// fp16 2-term GEMM: C = A @ (Whi + Wlo) + bias (+elu+1)
// BM=BN=128, BK=32, 256 threads, warp tile 64x32, cp.async 2-stage, 2 CTA/SM.
// z=0 writes fp32 (C0); z=1/2 write fp16 (H1/H2) when halfMask bit set.
// ---------------------------------------------------------------------------
#define ARR 10240            // 128 rows * 80B
#define STG (3 * ARR)        // 30720 per stage
#define GEMM_SMEM (2 * STG)  // 61440

__device__ __forceinline__ void load_stage(
    uint32_t sbase, int tid, int k0,
    const __half* pA, const __half* pWhi, const __half* pWlo)
{
#pragma unroll
    for (int rep = 0; rep < 2; rep++) {
        int l = rep * 256 + tid;        // 0..511
        int row = l >> 2;               // 0..127
        int ch = l & 3;                 // 0..3 (16B chunks)
        uint32_t so = sbase + (uint32_t)row * 80 + ch * 16;
        size_t go = (size_t)row * DM + k0 + ch * 8;
        CPASYNC16(so + 0 * ARR, pA + go);
        CPASYNC16(so + 1 * ARR, pWhi + go);
        CPASYNC16(so + 2 * ARR, pWlo + go);
    }
}

__global__ void __launch_bounds__(256, 2) gemm_f16(
    const __half* __restrict__ Ah,
    const __half* __restrict__ Whi, const __half* __restrict__ Wlo,
    const float* __restrict__ b0, const float* __restrict__ b1,
    const float* __restrict__ b2,
    float* __restrict__ C0, __half* __restrict__ H1, __half* __restrict__ H2,
    int actMask, int halfMask)
{
    extern __shared__ char smem[];
    const uint32_t sb = smem_u32(smem);
    const int z = blockIdx.z;
    const int tid = threadIdx.x;
    const int wid = tid >> 5;
    const int lid = tid & 31;
    const int rowBase = blockIdx.y * 128;
    const int colBase = blockIdx.x * 128;
    const int warpM = (wid >> 2) * 64;
    const int warpN = (wid & 3) * 32;

    const float* bias = (z == 0) ? b0 : (z == 1) ? b1 : b2;
    const int act = (actMask >> z) & 1;
    const int hout = (halfMask >> z) & 1;

    const __half* pA   = Ah  + (size_t)z * MROWS * DM + (size_t)rowBase * DM;
    const __half* pWhi = Whi + (size_t)z * DM * DM + (size_t)colBase * DM;
    const __half* pWlo = Wlo + (size_t)z * DM * DM + (size_t)colBase * DM;

    float acc[4][4][4];
#pragma unroll
    for (int i = 0; i < 4; i++)
#pragma unroll
        for (int j = 0; j < 4; j++)
#pragma unroll
            for (int e = 0; e < 4; e++) acc[i][j][e] = 0.f;

    load_stage(sb, tid, 0, pA, pWhi, pWlo);
    CPCOMMIT();

    const int aRow = warpM + (lid & 15);
    const uint32_t aCol = ((lid >> 4) & 1) * 16;
    const int bRow = warpN + (lid & 7);
    const uint32_t bCol = ((lid >> 3) & 1) * 16;

    for (int c = 0; c < 32; c++) {
        if (c + 1 < 32) {
            load_stage(sb + ((c + 1) & 1) * STG, tid, (c + 1) * 32,
                       pA, pWhi, pWlo);
            CPCOMMIT();
            CPWAIT1();
        } else {
            CPWAIT0();
        }
        __syncthreads();

        const uint32_t stage = sb + (c & 1) * STG;
#pragma unroll
        for (int kk = 0; kk < 2; kk++) {
            const uint32_t aOff = (uint32_t)kk * 32 + aCol;
            const uint32_t bOff = (uint32_t)kk * 32 + bCol;
            uint32_t fBhi[4][2], fBlo[4][2];
#pragma unroll
            for (int ni = 0; ni < 4; ni++) {
                uint32_t bd = stage + (uint32_t)(bRow + ni * 8) * 80 + bOff;
                ldsm2(fBhi[ni], bd + 1 * ARR);
                ldsm2(fBlo[ni], bd + 2 * ARR);
            }
#pragma unroll
            for (int mi = 0; mi < 4; mi++) {
                uint32_t fA[4];
                ldsm4(fA, stage + (uint32_t)(aRow + mi * 16) * 80 + aOff);
#pragma unroll
                for (int ni = 0; ni < 4; ni++) {
                    mma16816(acc[mi][ni], fA, fBhi[ni]);
                    mma16816(acc[mi][ni], fA, fBlo[ni]);
                }
            }
        }
        __syncthreads();
    }

    // epilogue: bias + optional elu+1; fp32 (z==0 / Wo) or fp16 (k,v)
    __half* H = (z == 1) ? H1 : H2;
#pragma unroll
    for (int mi = 0; mi < 4; mi++) {
        int r0 = rowBase + warpM + mi * 16 + (lid >> 2);
#pragma unroll
        for (int ni = 0; ni < 4; ni++) {
            int col = colBase + warpN + ni * 8 + (lid & 3) * 2;
            float2 b2v = *(const float2*)(bias + col);
            float v0 = acc[mi][ni][0] + b2v.x;
            float v1 = acc[mi][ni][1] + b2v.y;
            float v2 = acc[mi][ni][2] + b2v.x;
            float v3 = acc[mi][ni][3] + b2v.y;
            if (act) {
                v0 = (v0 > 0.f) ? (v0 + 1.f) : expf(v0);
                v1 = (v1 > 0.f) ? (v1 + 1.f) : expf(v1);
                v2 = (v2 > 0.f) ? (v2 + 1.f) : expf(v2);
                v3 = (v3 > 0.f) ? (v3 + 1.f) : expf(v3);
            }
            if (hout) {
                *(__half2*)(H + (size_t)r0 * DM + col)       = __floats2half2_rn(v0, v1);
                *(__half2*)(H + (size_t)(r0 + 8) * DM + col) = __floats2half2_rn(v2, v3);
            } else {
                float2 o0; o0.x = v0; o0.y = v1;
                float2 o1; o1.x = v2; o1.y = v3;
                *(float2*)(C0 + (size_t)r0 * DM + col) = o0;
                *(float2*)(C0 + (size_t)(r0 + 8) * DM + col) = o1;
            }
        }
    }
}

// ---------------------------------------------------------------------------
// Attention kernels (k/v read as fp16)
// ---------------------------------------------------------------------------
__global__ void __launch_bounds__(256) chunk_sums_kernel()
{
    const int c = blockIdx.x;
    const int nh = blockIdx.y;
    const int n = nh >> 4;
    const int h = nh & 15;
    const int tid = threadIdx.x;

    __shared__ float Ks[64][68];
    __shared__ float Vs[64][68];

    const size_t rowbase = ((size_t)(n * LSEQ + c * CH)) * DM + h * HD;

    // fp16 loads: 64 rows x 64 halves = 512 uint4, 2 reps
#pragma unroll
    for (int rep = 0; rep < 2; rep++) {
        int idx = rep * 256 + tid;      // 0..511
        int i  = idx >> 3;              // row
        int j8 = (idx & 7) * 8;         // col base
        uint4 ku = *(const uint4*)(g_kh + rowbase + (size_t)i * DM + j8);
        uint4 vu = *(const uint4*)(g_vh + rowbase + (size_t)i * DM + j8);
        const __half2* kh2 = (const __half2*)&ku;
        const __half2* vh2 = (const __half2*)&vu;
#pragma unroll
        for (int t = 0; t < 4; t++) {
            float2 kf = __half22float2(kh2[t]);
            float2 vf = __half22float2(vh2[t]);
            Ks[i][j8 + t * 2 + 0] = kf.x;
            Ks[i][j8 + t * 2 + 1] = kf.y;
            Vs[i][j8 + t * 2 + 0] = vf.x;
            Vs[i][j8 + t * 2 + 1] = vf.y;
        }
    }
    __syncthreads();

    const int td = (tid >> 4) * 4;
    const int tk = (tid & 15) * 4;
    float acc[4][4];
#pragma unroll
    for (int a = 0; a < 4; a++)
#pragma unroll
        for (int b = 0; b < 4; b++) acc[a][b] = 0.f;

    for (int i = 0; i < 64; i++) {
        float ka[4];
        ka[0] = Ks[i][td + 0]; ka[1] = Ks[i][td + 1];
        ka[2] = Ks[i][td + 2]; ka[3] = Ks[i][td + 3];
        float4 vv = *(const float4*)&Vs[i][tk];
        float vb[4] = {vv.x, vv.y, vv.z, vv.w};
#pragma unroll
        for (int a = 0; a < 4; a++)
#pragma unroll
            for (int b = 0; b < 4; b++)
                acc[a][b] = fmaf(ka[a], vb[b], acc[a][b]);
    }

    float* Sp = g_S + ((size_t)nh * NC + c) * (HD * HD);
#pragma unroll
    for (int a = 0; a < 4; a++) {
        float4 o; o.x=acc[a][0]; o.y=acc[a][1]; o.z=acc[a][2]; o.w=acc[a][3];
        *(float4*)&Sp[(td + a) * HD + tk] = o;
    }

    if (tid < 64) {
        float s = 0.f;
        for (int i = 0; i < 64; i++)
            s += g_qp[rowbase + (size_t)i * DM + tid];
        g_qs[((size_t)nh * NC + c) * HD + tid] = s;
    }
}

// Parallel prefix: grid (NH, 8), 256 threads; each thread scans 2 elements.
__global__ void __launch_bounds__(256) prefix_kernel()
{
    const int nh = blockIdx.x;
    const int seg = blockIdx.y;     // 0..7
    const int tid = threadIdx.x;
    const int e0 = seg * 512 + tid; // elements e0, e0+256

    float r0 = 0.f, r1 = 0.f;
    for (int c = 0; c < NC; c++) {
        float* Sp = g_S + ((size_t)nh * NC + c) * (HD * HD);
        float t0 = Sp[e0];       Sp[e0] = r0;       r0 += t0;
        float t1 = Sp[e0 + 256]; Sp[e0 + 256] = r1; r1 += t1;
    }

    if (seg == 0 && tid < 64) {
        float r = 0.f;
        for (int c = 0; c < NC; c++) {
            float* qp = g_qs + ((size_t)nh * NC + c) * HD + tid;
            float t = *qp;
            *qp = r;
            r += t;
        }
    }
}

// chunk_out: O = (tril(Qp Kp^T) V + Qp P) / Z, written fp16 into g_Ah[0]
#define TS (64 * 68)
__global__ void __launch_bounds__(256) chunk_out_kernel()
{
    extern __shared__ float fsm[];
    float* Qs = fsm;
    float* Kt = fsm + TS;
    float* Vs = fsm + 2 * TS;
    float* Ps = fsm + 3 * TS;
    float* As = fsm + 4 * TS;

    const int c = blockIdx.x;
    const int nh = blockIdx.y;
    const int n = nh >> 4;
    const int h = nh & 15;
    const int tid = threadIdx.x;

    const size_t rowbase = ((size_t)(n * LSEQ + c * CH)) * DM + h * HD;
    const float* Sp = g_S + ((size_t)nh * NC + c) * (HD * HD);

    // Q (fp32) and P (fp32): 4 reps of float4
#pragma unroll
    for (int rep = 0; rep < 4; rep++) {
        int idx = rep * 256 + tid;
        int i  = idx >> 4;
        int j4 = (idx & 15) * 4;
        float4 q = *(const float4*)(g_qp + rowbase + (size_t)i * DM + j4);
        *(float4*)&Qs[i * 68 + j4] = q;
        float4 p = *(const float4*)(Sp + idx * 4);
        int d = (idx * 4) >> 6;
        int kk = (idx * 4) & 63;
        *(float4*)&Ps[d * 68 + kk] = p;
    }
    // K (fp16, transposed) and V (fp16): 2 reps of uint4 (8 halves)
#pragma unroll
    for (int rep = 0; rep < 2; rep++) {
        int idx = rep * 256 + tid;      // 0..511
        int i  = idx >> 3;
        int j8 = (idx & 7) * 8;
        uint4 ku = *(const uint4*)(g_kh + rowbase + (size_t)i * DM + j8);
        uint4 vu = *(const uint4*)(g_vh + rowbase + (size_t)i * DM + j8);
        const __half2* kh2 = (const __half2*)&ku;
        const __half2* vh2 = (const __half2*)&vu;
#pragma unroll
        for (int t = 0; t < 4; t++) {
            float2 kf = __half22float2(kh2[t]);
            float2 vf = __half22float2(vh2[t]);
            Kt[(j8 + t * 2 + 0) * 68 + i] = kf.x;
            Kt[(j8 + t * 2 + 1) * 68 + i] = kf.y;
            Vs[i * 68 + j8 + t * 2 + 0] = vf.x;
            Vs[i * 68 + j8 + t * 2 + 1] = vf.y;
        }
    }
    __syncthreads();

    const int ti = (tid >> 4) * 4;
    const int tj = (tid & 15) * 4;

    {
        float acc[4][4];
#pragma unroll
        for (int a = 0; a < 4; a++)
#pragma unroll
            for (int b = 0; b < 4; b++) acc[a][b] = 0.f;
        for (int d = 0; d < 64; d++) {
            float qa[4];
            qa[0] = Qs[(ti + 0) * 68 + d]; qa[1] = Qs[(ti + 1) * 68 + d];
            qa[2] = Qs[(ti + 2) * 68 + d]; qa[3] = Qs[(ti + 3) * 68 + d];
            float4 kb = *(const float4*)&Kt[d * 68 + tj];
            float kv[4] = {kb.x, kb.y, kb.z, kb.w};
#pragma unroll
            for (int a = 0; a < 4; a++)
#pragma unroll
                for (int b = 0; b < 4; b++)
                    acc[a][b] = fmaf(qa[a], kv[b], acc[a][b]);
        }
#pragma unroll
        for (int a = 0; a < 4; a++) {
            float4 o;
            o.x = (tj + 0 <= ti + a) ? acc[a][0] : 0.f;
            o.y = (tj + 1 <= ti + a) ? acc[a][1] : 0.f;
            o.z = (tj + 2 <= ti + a) ? acc[a][2] : 0.f;
            o.w = (tj + 3 <= ti + a) ? acc[a][3] : 0.f;
            *(float4*)&As[(ti + a) * 68 + tj] = o;
        }
    }
    __syncthreads();

    float* Zc = Kt;   // reuse
    __syncthreads();
    if (tid < 64) {
        float z = g_qs[((size_t)nh * NC + c) * HD + tid];
        for (int i = 0; i < 64; i++) {
            z += Qs[i * 68 + tid];
            Zc[i * 68 + tid] = z;
        }
    }
    __syncthreads();

    {
        const int tk = tj;
        float acc[4][4];
#pragma unroll
        for (int a = 0; a < 4; a++)
#pragma unroll
            for (int b = 0; b < 4; b++) acc[a][b] = 0.f;

        for (int j = 0; j < 64; j++) {
            float aa[4];
            aa[0] = As[(ti + 0) * 68 + j]; aa[1] = As[(ti + 1) * 68 + j];
            aa[2] = As[(ti + 2) * 68 + j]; aa[3] = As[(ti + 3) * 68 + j];
            float4 vv = *(const float4*)&Vs[j * 68 + tk];
            float vb[4] = {vv.x, vv.y, vv.z, vv.w};
#pragma unroll
            for (int a = 0; a < 4; a++)
#pragma unroll
                for (int b = 0; b < 4; b++)
                    acc[a][b] = fmaf(aa[a], vb[b], acc[a][b]);
        }
        for (int d = 0; d < 64; d++) {
            float qa[4];
            qa[0] = Qs[(ti + 0) * 68 + d]; qa[1] = Qs[(ti + 1) * 68 + d];
            qa[2] = Qs[(ti + 2) * 68 + d]; qa[3] = Qs[(ti + 3) * 68 + d];
            float4 pp = *(const float4*)&Ps[d * 68 + tk];
            float pb[4] = {pp.x, pp.y, pp.z, pp.w};
#pragma unroll
            for (int a = 0; a < 4; a++)
#pragma unroll
                for (int b = 0; b < 4; b++)
                    acc[a][b] = fmaf(qa[a], pb[b], acc[a][b]);
        }

#pragma unroll
        for (int a = 0; a < 4; a++) {
            float4 z4 = *(const float4*)&Zc[(ti + a) * 68 + tk];
            __half2 h01 = __floats2half2_rn(acc[a][0] / z4.x, acc[a][1] / z4.y);
            __half2 h23 = __floats2half2_rn(acc[a][2] / z4.z, acc[a][3] / z4.w);
            size_t eo = rowbase + (size_t)(ti + a) * DM + tk;
            *(__half2*)(g_Ah + eo)     = h01;
            *(__half2*)(g_Ah + eo + 2) = h23;
        }
    }
}

// ---------------------------------------------------------------------------
extern "C" void kernel_launch(void* const* d_in, const int* in_sizes, int n_in,
                              void* d_out, int out_size)
{
    const float* queries = (const float*)d_in[0];
    const float* keys    = (const float*)d_in[1];
    const float* values  = (const float*)d_in[2];
    const float* Wq = (const float*)d_in[3];
    const float* bq = (const float*)d_in[4];
    const float* Wk = (const float*)d_in[5];
    const float* bk = (const float*)d_in[6];
    const float* Wv = (const float*)d_in[7];
    const float* bv = (const float*)d_in[8];
    const float* Wo = (const float*)d_in[9];
    const float* bo = (const float*)d_in[10];
    float* out = (float*)d_out;

    float* qp;  cudaGetSymbolAddress((void**)&qp,  g_qp);
    __half* kh;  cudaGetSymbolAddress((void**)&kh,  g_kh);
    __half* vh;  cudaGetSymbolAddress((void**)&vh,  g_vh);
    __half* ah;  cudaGetSymbolAddress((void**)&ah,  g_Ah);
    __half* whi; cudaGetSymbolAddress((void**)&whi, g_Whi);
    __half* wlo; cudaGetSymbolAddress((void**)&wlo, g_Wlo);

    static bool attrSet = false;
    if (!attrSet) {
        cudaFuncSetAttribute(gemm_f16, cudaFuncAttributeMaxDynamicSharedMemorySize,
                             GEMM_SMEM);
        cudaFuncSetAttribute(chunk_out_kernel,
                             cudaFuncAttributeMaxDynamicSharedMemorySize,
                             (int)(5 * TS * sizeof(float)));
        attrSet = true;
    }

    const int splitBlocks = (MROWS * DM / 4 + 255) / 256;

    // Split inputs and all 4 weights (batched)
    split_input3<<<dim3(splitBlocks, 3), 256>>>(queries, keys, values,
                                                MROWS * DM / 4);
    transpose_split4<<<dim3(DM / 32, DM / 32, 4), 256>>>(Wq, Wk, Wv, Wo);

    // Fused Q/K/V projections: q -> fp32 g_qp, k/v -> fp16 g_kh/g_vh
    gemm_f16<<<dim3(DM / 128, MROWS / 128, 3), 256, GEMM_SMEM>>>(
        ah, whi, wlo, bq, bk, bv, qp, kh, vh, 0x3, 0x6);

    // Chunked causal linear attention
    dim3 chunkGrid(NC, NH);
    chunk_sums_kernel<<<chunkGrid, 256>>>();
    prefix_kernel<<<dim3(NH, 8), 256>>>();
    chunk_out_kernel<<<chunkGrid, 256, 5 * TS * sizeof(float)>>>();

    // Output projection: att (slot 0 of g_Ah) @ Wo (slot 3) + bo -> fp32 out
    gemm_f16<<<dim3(DM / 128, MROWS / 128, 1), 256, GEMM_SMEM>>>(
        ah, whi + 3 * (size_t)DM * DM, wlo + 3 * (size_t)DM * DM,
        bo, bo, bo, out, kh, vh, 0x0, 0x0);
}

// round 7
// speedup vs baseline: 3.1015x; 1.0457x over previous
#include <cuda_runtime.h>
#include <cuda_fp16.h>
#include <math.h>
#include <cstdint>

// Problem constants
#define NB 4
#define LSEQ 2048
#define DM 1024
#define NHEAD 16
#define HD 64
#define MROWS (NB * LSEQ)   // 8192
#define CH 64
#define NC (LSEQ / CH)      // 32
#define NH (NB * NHEAD)     // 64

// Scratch (device globals; no allocation allowed)
__device__ float g_qp[MROWS * DM];          // elu(q)+1 fp32 (needed for Z)
__device__ __half g_kh[MROWS * DM];         // elu(k)+1 fp16
__device__ __half g_vh[MROWS * DM];         // v projection fp16
__device__ float g_S [NH * NC * HD * HD];
__device__ float g_qs[NH * NC * HD];

// fp16 GEMM operand scratch
__device__ __half g_Ah [3 * MROWS * DM];    // q,k,v inputs (att reuses slot 0)
__device__ __half g_Whi[4 * DM * DM];       // transposed [n][k]; slot 3 = Wo
__device__ __half g_Wlo[4 * DM * DM];

// ---------------------------------------------------------------------------
// PTX helpers
// ---------------------------------------------------------------------------
__device__ __forceinline__ uint32_t smem_u32(const void* p) {
    uint32_t a;
    asm("{ .reg .u64 t; cvta.to.shared.u64 t, %1; cvt.u32.u64 %0, t; }"
        : "=r"(a) : "l"(p));
    return a;
}

#define CPASYNC16(s, g) \
    asm volatile("cp.async.cg.shared.global [%0], [%1], 16;" \
                 :: "r"(s), "l"(g) : "memory")
#define CPCOMMIT() asm volatile("cp.async.commit_group;" ::: "memory")
#define CPWAIT1()  asm volatile("cp.async.wait_group 1;" ::: "memory")
#define CPWAIT0()  asm volatile("cp.async.wait_group 0;" ::: "memory")

__device__ __forceinline__ void ldsm4(uint32_t* r, uint32_t a) {
    asm volatile("ldmatrix.sync.aligned.m8n8.x4.shared.b16 {%0,%1,%2,%3}, [%4];"
        : "=r"(r[0]), "=r"(r[1]), "=r"(r[2]), "=r"(r[3]) : "r"(a));
}
__device__ __forceinline__ void ldsm2(uint32_t* r, uint32_t a) {
    asm volatile("ldmatrix.sync.aligned.m8n8.x2.shared.b16 {%0,%1}, [%2];"
        : "=r"(r[0]), "=r"(r[1]) : "r"(a));
}
__device__ __forceinline__ void mma16816(float* c, const uint32_t* a, const uint32_t* b) {
    asm volatile("mma.sync.aligned.m16n8k16.row.col.f32.f16.f16.f32 "
        "{%0,%1,%2,%3}, {%4,%5,%6,%7}, {%8,%9}, {%0,%1,%2,%3};"
        : "+f"(c[0]), "+f"(c[1]), "+f"(c[2]), "+f"(c[3])
        : "r"(a[0]), "r"(a[1]), "r"(a[2]), "r"(a[3]), "r"(b[0]), "r"(b[1]));
}

// ---------------------------------------------------------------------------
// split_input3: fp32 -> fp16, batched over z = {q,k,v}
// ---------------------------------------------------------------------------
__global__ void __launch_bounds__(256) split_input3(
    const float* __restrict__ Xq, const float* __restrict__ Xk,
    const float* __restrict__ Xv, int n4)
{
    int z = blockIdx.y;
    const float* X = (z == 0) ? Xq : (z == 1) ? Xk : Xv;
    __half* out = g_Ah + (size_t)z * MROWS * DM;
    int idx = blockIdx.x * 256 + threadIdx.x;
    if (idx >= n4) return;
    float4 x = ((const float4*)X)[idx];
    __half2* op = (__half2*)out;
    op[idx * 2 + 0] = __floats2half2_rn(x.x, x.y);
    op[idx * 2 + 1] = __floats2half2_rn(x.z, x.w);
}

// transpose_split4: W[k][n] fp32 -> Wt hi/lo fp16 [n][k], batched over 4 weights
__global__ void __launch_bounds__(256) transpose_split4(
    const float* __restrict__ W0, const float* __restrict__ W1,
    const float* __restrict__ W2, const float* __restrict__ W3)
{
    __shared__ float t[32][33];
    int z = blockIdx.z;
    const float* W = (z == 0) ? W0 : (z == 1) ? W1 : (z == 2) ? W2 : W3;
    __half* hi = g_Whi + (size_t)z * DM * DM;
    __half* lo = g_Wlo + (size_t)z * DM * DM;
    int bx = blockIdx.x * 32;   // n base
    int by = blockIdx.y * 32;   // k base
    int tx = threadIdx.x & 31;
    int ty = threadIdx.x >> 5;  // 0..7
#pragma unroll
    for (int i = 0; i < 4; i++) {
        int k = by + ty + i * 8;
        t[ty + i * 8][tx] = W[(size_t)k * DM + bx + tx];
    }
    __syncthreads();
#pragma unroll
    for (int i = 0; i < 4; i++) {
        int n = bx + ty + i * 8;
        int k = by + tx;
        float v = t[tx][ty + i * 8];
        __half h = __float2half_rn(v);
        __half l = __float2half_rn(v - __half2float(h));
        hi[(size_t)n * DM + k] = h;
        lo[(size_t)n * DM + k] = l;
    }
}

// ---------------------------------------------------------------------------
// fp16 2-term GEMM: C = A @ (Whi + Wlo) + bias (+elu+1)
// ---------------------------------------------------------------------------
#define ARR 10240            // 128 rows * 80B
#define STG (3 * ARR)        // 30720 per stage
#define GEMM_SMEM (2 * STG)  // 61440

__device__ __forceinline__ void load_stage(
    uint32_t sbase, int tid, int k0,
    const __half* pA, const __half* pWhi, const __half* pWlo)
{
#pragma unroll
    for (int rep = 0; rep < 2; rep++) {
        int l = rep * 256 + tid;        // 0..511
        int row = l >> 2;               // 0..127
        int ch = l & 3;                 // 0..3 (16B chunks)
        uint32_t so = sbase + (uint32_t)row * 80 + ch * 16;
        size_t go = (size_t)row * DM + k0 + ch * 8;
        CPASYNC16(so + 0 * ARR, pA + go);
        CPASYNC16(so + 1 * ARR, pWhi + go);
        CPASYNC16(so + 2 * ARR, pWlo + go);
    }
}

__global__ void __launch_bounds__(256, 2) gemm_f16(
    const __half* __restrict__ Ah,
    const __half* __restrict__ Whi, const __half* __restrict__ Wlo,
    const float* __restrict__ b0, const float* __restrict__ b1,
    const float* __restrict__ b2,
    float* __restrict__ C0, __half* __restrict__ H1, __half* __restrict__ H2,
    int actMask, int halfMask)
{
    extern __shared__ char smem[];
    const uint32_t sb = smem_u32(smem);
    const int z = blockIdx.z;
    const int tid = threadIdx.x;
    const int wid = tid >> 5;
    const int lid = tid & 31;
    const int rowBase = blockIdx.y * 128;
    const int colBase = blockIdx.x * 128;
    const int warpM = (wid >> 2) * 64;
    const int warpN = (wid & 3) * 32;

    const float* bias = (z == 0) ? b0 : (z == 1) ? b1 : b2;
    const int act = (actMask >> z) & 1;
    const int hout = (halfMask >> z) & 1;

    const __half* pA   = Ah  + (size_t)z * MROWS * DM + (size_t)rowBase * DM;
    const __half* pWhi = Whi + (size_t)z * DM * DM + (size_t)colBase * DM;
    const __half* pWlo = Wlo + (size_t)z * DM * DM + (size_t)colBase * DM;

    float acc[4][4][4];
#pragma unroll
    for (int i = 0; i < 4; i++)
#pragma unroll
        for (int j = 0; j < 4; j++)
#pragma unroll
            for (int e = 0; e < 4; e++) acc[i][j][e] = 0.f;

    load_stage(sb, tid, 0, pA, pWhi, pWlo);
    CPCOMMIT();

    const int aRow = warpM + (lid & 15);
    const uint32_t aCol = ((lid >> 4) & 1) * 16;
    const int bRow = warpN + (lid & 7);
    const uint32_t bCol = ((lid >> 3) & 1) * 16;

    for (int c = 0; c < 32; c++) {
        if (c + 1 < 32) {
            load_stage(sb + ((c + 1) & 1) * STG, tid, (c + 1) * 32,
                       pA, pWhi, pWlo);
            CPCOMMIT();
            CPWAIT1();
        } else {
            CPWAIT0();
        }
        __syncthreads();

        const uint32_t stage = sb + (c & 1) * STG;
#pragma unroll
        for (int kk = 0; kk < 2; kk++) {
            const uint32_t aOff = (uint32_t)kk * 32 + aCol;
            const uint32_t bOff = (uint32_t)kk * 32 + bCol;
            uint32_t fBhi[4][2], fBlo[4][2];
#pragma unroll
            for (int ni = 0; ni < 4; ni++) {
                uint32_t bd = stage + (uint32_t)(bRow + ni * 8) * 80 + bOff;
                ldsm2(fBhi[ni], bd + 1 * ARR);
                ldsm2(fBlo[ni], bd + 2 * ARR);
            }
#pragma unroll
            for (int mi = 0; mi < 4; mi++) {
                uint32_t fA[4];
                ldsm4(fA, stage + (uint32_t)(aRow + mi * 16) * 80 + aOff);
#pragma unroll
                for (int ni = 0; ni < 4; ni++) {
                    mma16816(acc[mi][ni], fA, fBhi[ni]);
                    mma16816(acc[mi][ni], fA, fBlo[ni]);
                }
            }
        }
        __syncthreads();
    }

    // epilogue
    __half* H = (z == 1) ? H1 : H2;
#pragma unroll
    for (int mi = 0; mi < 4; mi++) {
        int r0 = rowBase + warpM + mi * 16 + (lid >> 2);
#pragma unroll
        for (int ni = 0; ni < 4; ni++) {
            int col = colBase + warpN + ni * 8 + (lid & 3) * 2;
            float2 b2v = *(const float2*)(bias + col);
            float v0 = acc[mi][ni][0] + b2v.x;
            float v1 = acc[mi][ni][1] + b2v.y;
            float v2 = acc[mi][ni][2] + b2v.x;
            float v3 = acc[mi][ni][3] + b2v.y;
            if (act) {
                v0 = (v0 > 0.f) ? (v0 + 1.f) : expf(v0);
                v1 = (v1 > 0.f) ? (v1 + 1.f) : expf(v1);
                v2 = (v2 > 0.f) ? (v2 + 1.f) : expf(v2);
                v3 = (v3 > 0.f) ? (v3 + 1.f) : expf(v3);
            }
            if (hout) {
                *(__half2*)(H + (size_t)r0 * DM + col)       = __floats2half2_rn(v0, v1);
                *(__half2*)(H + (size_t)(r0 + 8) * DM + col) = __floats2half2_rn(v2, v3);
            } else {
                float2 o0; o0.x = v0; o0.y = v1;
                float2 o1; o1.x = v2; o1.y = v3;
                *(float2*)(C0 + (size_t)r0 * DM + col) = o0;
                *(float2*)(C0 + (size_t)(r0 + 8) * DM + col) = o1;
            }
        }
    }
}

// ---------------------------------------------------------------------------
// Attention kernels
// ---------------------------------------------------------------------------
__global__ void __launch_bounds__(256) chunk_sums_kernel()
{
    const int c = blockIdx.x;
    const int nh = blockIdx.y;
    const int n = nh >> 4;
    const int h = nh & 15;
    const int tid = threadIdx.x;

    __shared__ float Ks[64][68];
    __shared__ float Vs[64][68];
    __shared__ float qsum[4][72];

    const size_t rowbase = ((size_t)(n * LSEQ + c * CH)) * DM + h * HD;

    // qp partial column sums: 256 threads, each sums 16 rows of one column
    {
        int col = tid & 63;
        int qtr = tid >> 6;     // 0..3
        float s = 0.f;
        const float* qb = g_qp + rowbase + (size_t)(qtr * 16) * DM + col;
#pragma unroll
        for (int i = 0; i < 16; i++)
            s += qb[(size_t)i * DM];
        qsum[qtr][col] = s;
    }

    // fp16 K/V loads: 64 rows x 64 halves = 512 uint4, 2 reps
#pragma unroll
    for (int rep = 0; rep < 2; rep++) {
        int idx = rep * 256 + tid;      // 0..511
        int i  = idx >> 3;              // row
        int j8 = (idx & 7) * 8;         // col base
        uint4 ku = *(const uint4*)(g_kh + rowbase + (size_t)i * DM + j8);
        uint4 vu = *(const uint4*)(g_vh + rowbase + (size_t)i * DM + j8);
        const __half2* kh2 = (const __half2*)&ku;
        const __half2* vh2 = (const __half2*)&vu;
#pragma unroll
        for (int t = 0; t < 4; t++) {
            float2 kf = __half22float2(kh2[t]);
            float2 vf = __half22float2(vh2[t]);
            Ks[i][j8 + t * 2 + 0] = kf.x;
            Ks[i][j8 + t * 2 + 1] = kf.y;
            Vs[i][j8 + t * 2 + 0] = vf.x;
            Vs[i][j8 + t * 2 + 1] = vf.y;
        }
    }
    __syncthreads();

    const int td = (tid >> 4) * 4;
    const int tk = (tid & 15) * 4;
    float acc[4][4];
#pragma unroll
    for (int a = 0; a < 4; a++)
#pragma unroll
        for (int b = 0; b < 4; b++) acc[a][b] = 0.f;

    for (int i = 0; i < 64; i++) {
        float ka[4];
        ka[0] = Ks[i][td + 0]; ka[1] = Ks[i][td + 1];
        ka[2] = Ks[i][td + 2]; ka[3] = Ks[i][td + 3];
        float4 vv = *(const float4*)&Vs[i][tk];
        float vb[4] = {vv.x, vv.y, vv.z, vv.w};
#pragma unroll
        for (int a = 0; a < 4; a++)
#pragma unroll
            for (int b = 0; b < 4; b++)
                acc[a][b] = fmaf(ka[a], vb[b], acc[a][b]);
    }

    float* Sp = g_S + ((size_t)nh * NC + c) * (HD * HD);
#pragma unroll
    for (int a = 0; a < 4; a++) {
        float4 o; o.x=acc[a][0]; o.y=acc[a][1]; o.z=acc[a][2]; o.w=acc[a][3];
        *(float4*)&Sp[(td + a) * HD + tk] = o;
    }

    if (tid < 64) {
        float s = qsum[0][tid] + qsum[1][tid] + qsum[2][tid] + qsum[3][tid];
        g_qs[((size_t)nh * NC + c) * HD + tid] = s;
    }
}

// Parallel prefix: grid (NH, 8), 256 threads; each thread scans 2 elements.
__global__ void __launch_bounds__(256) prefix_kernel()
{
    const int nh = blockIdx.x;
    const int seg = blockIdx.y;     // 0..7
    const int tid = threadIdx.x;
    const int e0 = seg * 512 + tid; // elements e0, e0+256

    float r0 = 0.f, r1 = 0.f;
    for (int c = 0; c < NC; c++) {
        float* Sp = g_S + ((size_t)nh * NC + c) * (HD * HD);
        float t0 = Sp[e0];       Sp[e0] = r0;       r0 += t0;
        float t1 = Sp[e0 + 256]; Sp[e0 + 256] = r1; r1 += t1;
    }

    if (seg == 0 && tid < 64) {
        float r = 0.f;
        for (int c = 0; c < NC; c++) {
            float* qp = g_qs + ((size_t)nh * NC + c) * HD + tid;
            float t = *qp;
            *qp = r;
            r += t;
        }
    }
}

// chunk_out: O = (tril(Qp Kp^T) V + Qp P) / Z, fp16 out into g_Ah[0].
// 4 smem arrays (68KB) -> 2 CTAs/SM. A-tile kept in registers; As reuses Ps
// slot, Zc reuses Kt slot.
#define TS (64 * 68)
#define CO_SMEM (4 * TS * 4)   // 69632 bytes
__global__ void __launch_bounds__(256, 2) chunk_out_kernel()
{
    extern __shared__ float fsm[];
    float* Qs = fsm;            // [i][d]
    float* Kt = fsm + TS;       // [d][i]  -> Zc later
    float* Vs = fsm + 2 * TS;   // [j][k]
    float* Ps = fsm + 3 * TS;   // [d][k]  -> As later

    const int c = blockIdx.x;
    const int nh = blockIdx.y;
    const int n = nh >> 4;
    const int h = nh & 15;
    const int tid = threadIdx.x;

    const size_t rowbase = ((size_t)(n * LSEQ + c * CH)) * DM + h * HD;
    const float* Sp = g_S + ((size_t)nh * NC + c) * (HD * HD);

    // Q (fp32) and P (fp32)
#pragma unroll
    for (int rep = 0; rep < 4; rep++) {
        int idx = rep * 256 + tid;
        int i  = idx >> 4;
        int j4 = (idx & 15) * 4;
        float4 q = *(const float4*)(g_qp + rowbase + (size_t)i * DM + j4);
        *(float4*)&Qs[i * 68 + j4] = q;
        float4 p = *(const float4*)(Sp + idx * 4);
        int d = (idx * 4) >> 6;
        int kk = (idx * 4) & 63;
        *(float4*)&Ps[d * 68 + kk] = p;
    }
    // K (fp16, transposed) and V (fp16)
#pragma unroll
    for (int rep = 0; rep < 2; rep++) {
        int idx = rep * 256 + tid;      // 0..511
        int i  = idx >> 3;
        int j8 = (idx & 7) * 8;
        uint4 ku = *(const uint4*)(g_kh + rowbase + (size_t)i * DM + j8);
        uint4 vu = *(const uint4*)(g_vh + rowbase + (size_t)i * DM + j8);
        const __half2* kh2 = (const __half2*)&ku;
        const __half2* vh2 = (const __half2*)&vu;
#pragma unroll
        for (int t = 0; t < 4; t++) {
            float2 kf = __half22float2(kh2[t]);
            float2 vf = __half22float2(vh2[t]);
            Kt[(j8 + t * 2 + 0) * 68 + i] = kf.x;
            Kt[(j8 + t * 2 + 1) * 68 + i] = kf.y;
            Vs[i * 68 + j8 + t * 2 + 0] = vf.x;
            Vs[i * 68 + j8 + t * 2 + 1] = vf.y;
        }
    }
    __syncthreads();

    const int ti = (tid >> 4) * 4;
    const int tj = (tid & 15) * 4;   // doubles as tk for output columns

    float accO[4][4];   // output accumulator (starts with Q·P)
    float at[4][4];     // A tile = masked(Q·Kt)
#pragma unroll
    for (int a = 0; a < 4; a++)
#pragma unroll
        for (int b = 0; b < 4; b++) { accO[a][b] = 0.f; at[a][b] = 0.f; }

    // fused loop over d: one Qs read feeds both Q·P and Q·Kt^T
    for (int d = 0; d < 64; d++) {
        float qa[4];
        qa[0] = Qs[(ti + 0) * 68 + d]; qa[1] = Qs[(ti + 1) * 68 + d];
        qa[2] = Qs[(ti + 2) * 68 + d]; qa[3] = Qs[(ti + 3) * 68 + d];
        float4 pp = *(const float4*)&Ps[d * 68 + tj];
        float4 kb = *(const float4*)&Kt[d * 68 + tj];
        float pb[4] = {pp.x, pp.y, pp.z, pp.w};
        float kv[4] = {kb.x, kb.y, kb.z, kb.w};
#pragma unroll
        for (int a = 0; a < 4; a++)
#pragma unroll
            for (int b = 0; b < 4; b++) {
                accO[a][b] = fmaf(qa[a], pb[b], accO[a][b]);
                at[a][b]   = fmaf(qa[a], kv[b], at[a][b]);
            }
    }
    // causal mask
#pragma unroll
    for (int a = 0; a < 4; a++)
#pragma unroll
        for (int b = 0; b < 4; b++)
            if (tj + b > ti + a) at[a][b] = 0.f;

    __syncthreads();   // all reads of Ps/Kt complete

    // write A into Ps slot; Z cumsum into Kt slot
    float* As = Ps;
    float* Zc = Kt;
#pragma unroll
    for (int a = 0; a < 4; a++) {
        float4 o; o.x = at[a][0]; o.y = at[a][1]; o.z = at[a][2]; o.w = at[a][3];
        *(float4*)&As[(ti + a) * 68 + tj] = o;
    }
    if (tid < 64) {
        float z = g_qs[((size_t)nh * NC + c) * HD + tid];
        for (int i = 0; i < 64; i++) {
            z += Qs[i * 68 + tid];
            Zc[i * 68 + tid] = z;
        }
    }
    __syncthreads();

    // accO += A·V, divide by Z, store fp16
    for (int j = 0; j < 64; j++) {
        float aa[4];
        aa[0] = As[(ti + 0) * 68 + j]; aa[1] = As[(ti + 1) * 68 + j];
        aa[2] = As[(ti + 2) * 68 + j]; aa[3] = As[(ti + 3) * 68 + j];
        float4 vv = *(const float4*)&Vs[j * 68 + tj];
        float vb[4] = {vv.x, vv.y, vv.z, vv.w};
#pragma unroll
        for (int a = 0; a < 4; a++)
#pragma unroll
            for (int b = 0; b < 4; b++)
                accO[a][b] = fmaf(aa[a], vb[b], accO[a][b]);
    }

#pragma unroll
    for (int a = 0; a < 4; a++) {
        float4 z4 = *(const float4*)&Zc[(ti + a) * 68 + tj];
        __half2 h01 = __floats2half2_rn(accO[a][0] / z4.x, accO[a][1] / z4.y);
        __half2 h23 = __floats2half2_rn(accO[a][2] / z4.z, accO[a][3] / z4.w);
        size_t eo = rowbase + (size_t)(ti + a) * DM + tj;
        *(__half2*)(g_Ah + eo)     = h01;
        *(__half2*)(g_Ah + eo + 2) = h23;
    }
}

// ---------------------------------------------------------------------------
extern "C" void kernel_launch(void* const* d_in, const int* in_sizes, int n_in,
                              void* d_out, int out_size)
{
    const float* queries = (const float*)d_in[0];
    const float* keys    = (const float*)d_in[1];
    const float* values  = (const float*)d_in[2];
    const float* Wq = (const float*)d_in[3];
    const float* bq = (const float*)d_in[4];
    const float* Wk = (const float*)d_in[5];
    const float* bk = (const float*)d_in[6];
    const float* Wv = (const float*)d_in[7];
    const float* bv = (const float*)d_in[8];
    const float* Wo = (const float*)d_in[9];
    const float* bo = (const float*)d_in[10];
    float* out = (float*)d_out;

    float* qp;  cudaGetSymbolAddress((void**)&qp,  g_qp);
    __half* kh;  cudaGetSymbolAddress((void**)&kh,  g_kh);
    __half* vh;  cudaGetSymbolAddress((void**)&vh,  g_vh);
    __half* ah;  cudaGetSymbolAddress((void**)&ah,  g_Ah);
    __half* whi; cudaGetSymbolAddress((void**)&whi, g_Whi);
    __half* wlo; cudaGetSymbolAddress((void**)&wlo, g_Wlo);

    static bool attrSet = false;
    if (!attrSet) {
        cudaFuncSetAttribute(gemm_f16, cudaFuncAttributeMaxDynamicSharedMemorySize,
                             GEMM_SMEM);
        cudaFuncSetAttribute(chunk_out_kernel,
                             cudaFuncAttributeMaxDynamicSharedMemorySize,
                             CO_SMEM);
        attrSet = true;
    }

    const int splitBlocks = (MROWS * DM / 4 + 255) / 256;

    // Split inputs and all 4 weights (batched)
    split_input3<<<dim3(splitBlocks, 3), 256>>>(queries, keys, values,
                                                MROWS * DM / 4);
    transpose_split4<<<dim3(DM / 32, DM / 32, 4), 256>>>(Wq, Wk, Wv, Wo);

    // Fused Q/K/V projections: q -> fp32 g_qp, k/v -> fp16 g_kh/g_vh
    gemm_f16<<<dim3(DM / 128, MROWS / 128, 3), 256, GEMM_SMEM>>>(
        ah, whi, wlo, bq, bk, bv, qp, kh, vh, 0x3, 0x6);

    // Chunked causal linear attention
    dim3 chunkGrid(NC, NH);
    chunk_sums_kernel<<<chunkGrid, 256>>>();
    prefix_kernel<<<dim3(NH, 8), 256>>>();
    chunk_out_kernel<<<chunkGrid, 256, CO_SMEM>>>();

    // Output projection: att (slot 0 of g_Ah) @ Wo (slot 3) + bo -> fp32 out
    gemm_f16<<<dim3(DM / 128, MROWS / 128, 1), 256, GEMM_SMEM>>>(
        ah, whi + 3 * (size_t)DM * DM, wlo + 3 * (size_t)DM * DM,
        bo, bo, bo, out, kh, vh, 0x0, 0x0);
}

// round 8
// speedup vs baseline: 3.3177x; 1.0697x over previous
#include <cuda_runtime.h>
#include <cuda_fp16.h>
#include <math.h>
#include <cstdint>

// Problem constants
#define NB 4
#define LSEQ 2048
#define DM 1024
#define NHEAD 16
#define HD 64
#define MROWS (NB * LSEQ)   // 8192
#define CH 64
#define NC (LSEQ / CH)      // 32
#define NH (NB * NHEAD)     // 64

// Scratch (device globals; no allocation allowed)
__device__ float g_qp[MROWS * DM];          // elu(q)+1 fp32 (needed for Z)
__device__ __half g_kh[MROWS * DM];         // elu(k)+1 fp16
__device__ __half g_vh[MROWS * DM];         // v projection fp16
__device__ float g_S [NH * NC * HD * HD];
__device__ float g_qs[NH * NC * HD];

// fp16 GEMM operand scratch
__device__ __half g_Ah [3 * MROWS * DM];    // q,k,v inputs (att reuses slot 0)
__device__ __half g_Whi[4 * DM * DM];       // transposed [n][k]; slot 3 = Wo
__device__ __half g_Wlo[4 * DM * DM];

// ---------------------------------------------------------------------------
// PTX helpers
// ---------------------------------------------------------------------------
__device__ __forceinline__ uint32_t smem_u32(const void* p) {
    uint32_t a;
    asm("{ .reg .u64 t; cvta.to.shared.u64 t, %1; cvt.u32.u64 %0, t; }"
        : "=r"(a) : "l"(p));
    return a;
}

#define CPASYNC16(s, g) \
    asm volatile("cp.async.cg.shared.global [%0], [%1], 16;" \
                 :: "r"(s), "l"(g) : "memory")
#define CPCOMMIT() asm volatile("cp.async.commit_group;" ::: "memory")
#define CPWAIT1()  asm volatile("cp.async.wait_group 1;" ::: "memory")
#define CPWAIT0()  asm volatile("cp.async.wait_group 0;" ::: "memory")

__device__ __forceinline__ void ldsm4(uint32_t* r, uint32_t a) {
    asm volatile("ldmatrix.sync.aligned.m8n8.x4.shared.b16 {%0,%1,%2,%3}, [%4];"
        : "=r"(r[0]), "=r"(r[1]), "=r"(r[2]), "=r"(r[3]) : "r"(a));
}
__device__ __forceinline__ void ldsm2(uint32_t* r, uint32_t a) {
    asm volatile("ldmatrix.sync.aligned.m8n8.x2.shared.b16 {%0,%1}, [%2];"
        : "=r"(r[0]), "=r"(r[1]) : "r"(a));
}
__device__ __forceinline__ void mma16816(float* c, const uint32_t* a, const uint32_t* b) {
    asm volatile("mma.sync.aligned.m16n8k16.row.col.f32.f16.f16.f32 "
        "{%0,%1,%2,%3}, {%4,%5,%6,%7}, {%8,%9}, {%0,%1,%2,%3};"
        : "+f"(c[0]), "+f"(c[1]), "+f"(c[2]), "+f"(c[3])
        : "r"(a[0]), "r"(a[1]), "r"(a[2]), "r"(a[3]), "r"(b[0]), "r"(b[1]));
}

// ---------------------------------------------------------------------------
// split_input3: fp32 -> fp16, batched over z = {q,k,v}
// ---------------------------------------------------------------------------
__global__ void __launch_bounds__(256) split_input3(
    const float* __restrict__ Xq, const float* __restrict__ Xk,
    const float* __restrict__ Xv, int n4)
{
    int z = blockIdx.y;
    const float* X = (z == 0) ? Xq : (z == 1) ? Xk : Xv;
    __half* out = g_Ah + (size_t)z * MROWS * DM;
    int idx = blockIdx.x * 256 + threadIdx.x;
    if (idx >= n4) return;
    float4 x = ((const float4*)X)[idx];
    __half2* op = (__half2*)out;
    op[idx * 2 + 0] = __floats2half2_rn(x.x, x.y);
    op[idx * 2 + 1] = __floats2half2_rn(x.z, x.w);
}

// transpose_split4: W[k][n] fp32 -> Wt hi/lo fp16 [n][k], batched over 4 weights
__global__ void __launch_bounds__(256) transpose_split4(
    const float* __restrict__ W0, const float* __restrict__ W1,
    const float* __restrict__ W2, const float* __restrict__ W3)
{
    __shared__ float t[32][33];
    int z = blockIdx.z;
    const float* W = (z == 0) ? W0 : (z == 1) ? W1 : (z == 2) ? W2 : W3;
    __half* hi = g_Whi + (size_t)z * DM * DM;
    __half* lo = g_Wlo + (size_t)z * DM * DM;
    int bx = blockIdx.x * 32;   // n base
    int by = blockIdx.y * 32;   // k base
    int tx = threadIdx.x & 31;
    int ty = threadIdx.x >> 5;  // 0..7
#pragma unroll
    for (int i = 0; i < 4; i++) {
        int k = by + ty + i * 8;
        t[ty + i * 8][tx] = W[(size_t)k * DM + bx + tx];
    }
    __syncthreads();
#pragma unroll
    for (int i = 0; i < 4; i++) {
        int n = bx + ty + i * 8;
        int k = by + tx;
        float v = t[tx][ty + i * 8];
        __half h = __float2half_rn(v);
        __half l = __float2half_rn(v - __half2float(h));
        hi[(size_t)n * DM + k] = h;
        lo[(size_t)n * DM + k] = l;
    }
}

// ---------------------------------------------------------------------------
// fp16 GEMM: C = A @ (Whi [+ Wlo]) + bias (+elu+1)
// loMask bit z: 1 = 2-term (Whi+Wlo), 0 = single-term (Whi only)
// ---------------------------------------------------------------------------
#define ARR 10240            // 128 rows * 80B
#define STG (3 * ARR)        // 30720 per stage
#define GEMM_SMEM (2 * STG)  // 61440

__device__ __forceinline__ void load_stage(
    uint32_t sbase, int tid, int k0,
    const __half* pA, const __half* pWhi, const __half* pWlo, int loadLo)
{
#pragma unroll
    for (int rep = 0; rep < 2; rep++) {
        int l = rep * 256 + tid;        // 0..511
        int row = l >> 2;               // 0..127
        int ch = l & 3;                 // 0..3 (16B chunks)
        uint32_t so = sbase + (uint32_t)row * 80 + ch * 16;
        size_t go = (size_t)row * DM + k0 + ch * 8;
        CPASYNC16(so + 0 * ARR, pA + go);
        CPASYNC16(so + 1 * ARR, pWhi + go);
        if (loadLo) CPASYNC16(so + 2 * ARR, pWlo + go);
    }
}

__global__ void __launch_bounds__(256, 2) gemm_f16(
    const __half* __restrict__ Ah,
    const __half* __restrict__ Whi, const __half* __restrict__ Wlo,
    const float* __restrict__ b0, const float* __restrict__ b1,
    const float* __restrict__ b2,
    float* __restrict__ C0, __half* __restrict__ H1, __half* __restrict__ H2,
    int actMask, int halfMask, int loMask)
{
    extern __shared__ char smem[];
    const uint32_t sb = smem_u32(smem);
    const int z = blockIdx.z;
    const int tid = threadIdx.x;
    const int wid = tid >> 5;
    const int lid = tid & 31;
    const int rowBase = blockIdx.y * 128;
    const int colBase = blockIdx.x * 128;
    const int warpM = (wid >> 2) * 64;
    const int warpN = (wid & 3) * 32;

    const float* bias = (z == 0) ? b0 : (z == 1) ? b1 : b2;
    const int act = (actMask >> z) & 1;
    const int hout = (halfMask >> z) & 1;
    const int twoTerm = (loMask >> z) & 1;

    const __half* pA   = Ah  + (size_t)z * MROWS * DM + (size_t)rowBase * DM;
    const __half* pWhi = Whi + (size_t)z * DM * DM + (size_t)colBase * DM;
    const __half* pWlo = Wlo + (size_t)z * DM * DM + (size_t)colBase * DM;

    float acc[4][4][4];
#pragma unroll
    for (int i = 0; i < 4; i++)
#pragma unroll
        for (int j = 0; j < 4; j++)
#pragma unroll
            for (int e = 0; e < 4; e++) acc[i][j][e] = 0.f;

    load_stage(sb, tid, 0, pA, pWhi, pWlo, twoTerm);
    CPCOMMIT();

    const int aRow = warpM + (lid & 15);
    const uint32_t aCol = ((lid >> 4) & 1) * 16;
    const int bRow = warpN + (lid & 7);
    const uint32_t bCol = ((lid >> 3) & 1) * 16;

    for (int c = 0; c < 32; c++) {
        if (c + 1 < 32) {
            load_stage(sb + ((c + 1) & 1) * STG, tid, (c + 1) * 32,
                       pA, pWhi, pWlo, twoTerm);
            CPCOMMIT();
            CPWAIT1();
        } else {
            CPWAIT0();
        }
        __syncthreads();

        const uint32_t stage = sb + (c & 1) * STG;
#pragma unroll
        for (int kk = 0; kk < 2; kk++) {
            const uint32_t aOff = (uint32_t)kk * 32 + aCol;
            const uint32_t bOff = (uint32_t)kk * 32 + bCol;
            uint32_t fBhi[4][2], fBlo[4][2];
#pragma unroll
            for (int ni = 0; ni < 4; ni++) {
                uint32_t bd = stage + (uint32_t)(bRow + ni * 8) * 80 + bOff;
                ldsm2(fBhi[ni], bd + 1 * ARR);
                if (twoTerm) ldsm2(fBlo[ni], bd + 2 * ARR);
            }
#pragma unroll
            for (int mi = 0; mi < 4; mi++) {
                uint32_t fA[4];
                ldsm4(fA, stage + (uint32_t)(aRow + mi * 16) * 80 + aOff);
#pragma unroll
                for (int ni = 0; ni < 4; ni++) {
                    mma16816(acc[mi][ni], fA, fBhi[ni]);
                    if (twoTerm) mma16816(acc[mi][ni], fA, fBlo[ni]);
                }
            }
        }
        __syncthreads();
    }

    // epilogue
    __half* H = (z == 1) ? H1 : H2;
#pragma unroll
    for (int mi = 0; mi < 4; mi++) {
        int r0 = rowBase + warpM + mi * 16 + (lid >> 2);
#pragma unroll
        for (int ni = 0; ni < 4; ni++) {
            int col = colBase + warpN + ni * 8 + (lid & 3) * 2;
            float2 b2v = *(const float2*)(bias + col);
            float v0 = acc[mi][ni][0] + b2v.x;
            float v1 = acc[mi][ni][1] + b2v.y;
            float v2 = acc[mi][ni][2] + b2v.x;
            float v3 = acc[mi][ni][3] + b2v.y;
            if (act) {
                v0 = (v0 > 0.f) ? (v0 + 1.f) : expf(v0);
                v1 = (v1 > 0.f) ? (v1 + 1.f) : expf(v1);
                v2 = (v2 > 0.f) ? (v2 + 1.f) : expf(v2);
                v3 = (v3 > 0.f) ? (v3 + 1.f) : expf(v3);
            }
            if (hout) {
                *(__half2*)(H + (size_t)r0 * DM + col)       = __floats2half2_rn(v0, v1);
                *(__half2*)(H + (size_t)(r0 + 8) * DM + col) = __floats2half2_rn(v2, v3);
            } else {
                float2 o0; o0.x = v0; o0.y = v1;
                float2 o1; o1.x = v2; o1.y = v3;
                *(float2*)(C0 + (size_t)r0 * DM + col) = o0;
                *(float2*)(C0 + (size_t)(r0 + 8) * DM + col) = o1;
            }
        }
    }
}

// ---------------------------------------------------------------------------
// Attention kernels
// ---------------------------------------------------------------------------
__global__ void __launch_bounds__(256) chunk_sums_kernel()
{
    const int c = blockIdx.x;
    const int nh = blockIdx.y;
    const int n = nh >> 4;
    const int h = nh & 15;
    const int tid = threadIdx.x;

    __shared__ float Ks[64][68];
    __shared__ float Vs[64][68];
    __shared__ float qsum[4][72];

    const size_t rowbase = ((size_t)(n * LSEQ + c * CH)) * DM + h * HD;

    // qp partial column sums: 256 threads, each sums 16 rows of one column
    {
        int col = tid & 63;
        int qtr = tid >> 6;     // 0..3
        float s = 0.f;
        const float* qb = g_qp + rowbase + (size_t)(qtr * 16) * DM + col;
#pragma unroll
        for (int i = 0; i < 16; i++)
            s += qb[(size_t)i * DM];
        qsum[qtr][col] = s;
    }

    // fp16 K/V loads
#pragma unroll
    for (int rep = 0; rep < 2; rep++) {
        int idx = rep * 256 + tid;      // 0..511
        int i  = idx >> 3;              // row
        int j8 = (idx & 7) * 8;         // col base
        uint4 ku = *(const uint4*)(g_kh + rowbase + (size_t)i * DM + j8);
        uint4 vu = *(const uint4*)(g_vh + rowbase + (size_t)i * DM + j8);
        const __half2* kh2 = (const __half2*)&ku;
        const __half2* vh2 = (const __half2*)&vu;
#pragma unroll
        for (int t = 0; t < 4; t++) {
            float2 kf = __half22float2(kh2[t]);
            float2 vf = __half22float2(vh2[t]);
            Ks[i][j8 + t * 2 + 0] = kf.x;
            Ks[i][j8 + t * 2 + 1] = kf.y;
            Vs[i][j8 + t * 2 + 0] = vf.x;
            Vs[i][j8 + t * 2 + 1] = vf.y;
        }
    }
    __syncthreads();

    const int td = (tid >> 4) * 4;
    const int tk = (tid & 15) * 4;
    float acc[4][4];
#pragma unroll
    for (int a = 0; a < 4; a++)
#pragma unroll
        for (int b = 0; b < 4; b++) acc[a][b] = 0.f;

    for (int i = 0; i < 64; i++) {
        float ka[4];
        ka[0] = Ks[i][td + 0]; ka[1] = Ks[i][td + 1];
        ka[2] = Ks[i][td + 2]; ka[3] = Ks[i][td + 3];
        float4 vv = *(const float4*)&Vs[i][tk];
        float vb[4] = {vv.x, vv.y, vv.z, vv.w};
#pragma unroll
        for (int a = 0; a < 4; a++)
#pragma unroll
            for (int b = 0; b < 4; b++)
                acc[a][b] = fmaf(ka[a], vb[b], acc[a][b]);
    }

    float* Sp = g_S + ((size_t)nh * NC + c) * (HD * HD);
#pragma unroll
    for (int a = 0; a < 4; a++) {
        float4 o; o.x=acc[a][0]; o.y=acc[a][1]; o.z=acc[a][2]; o.w=acc[a][3];
        *(float4*)&Sp[(td + a) * HD + tk] = o;
    }

    if (tid < 64) {
        float s = qsum[0][tid] + qsum[1][tid] + qsum[2][tid] + qsum[3][tid];
        g_qs[((size_t)nh * NC + c) * HD + tid] = s;
    }
}

// Parallel prefix: grid (NH, 8), 256 threads; each thread scans 2 elements.
__global__ void __launch_bounds__(256) prefix_kernel()
{
    const int nh = blockIdx.x;
    const int seg = blockIdx.y;     // 0..7
    const int tid = threadIdx.x;
    const int e0 = seg * 512 + tid; // elements e0, e0+256

    float r0 = 0.f, r1 = 0.f;
    for (int c = 0; c < NC; c++) {
        float* Sp = g_S + ((size_t)nh * NC + c) * (HD * HD);
        float t0 = Sp[e0];       Sp[e0] = r0;       r0 += t0;
        float t1 = Sp[e0 + 256]; Sp[e0 + 256] = r1; r1 += t1;
    }

    if (seg == 0 && tid < 64) {
        float r = 0.f;
        for (int c = 0; c < NC; c++) {
            float* qp = g_qs + ((size_t)nh * NC + c) * HD + tid;
            float t = *qp;
            *qp = r;
            r += t;
        }
    }
}

// chunk_out: O = (tril(Qp Kp^T) V + Qp P) / Z, fp16 out into g_Ah[0].
#define TS (64 * 68)
#define CO_SMEM (4 * TS * 4)   // 69632 bytes
__global__ void __launch_bounds__(256, 2) chunk_out_kernel()
{
    extern __shared__ float fsm[];
    float* Qs = fsm;            // [i][d]
    float* Kt = fsm + TS;       // [d][i]  -> Zc later
    float* Vs = fsm + 2 * TS;   // [j][k]
    float* Ps = fsm + 3 * TS;   // [d][k]  -> As later

    const int c = blockIdx.x;
    const int nh = blockIdx.y;
    const int n = nh >> 4;
    const int h = nh & 15;
    const int tid = threadIdx.x;

    const size_t rowbase = ((size_t)(n * LSEQ + c * CH)) * DM + h * HD;
    const float* Sp = g_S + ((size_t)nh * NC + c) * (HD * HD);

#pragma unroll
    for (int rep = 0; rep < 4; rep++) {
        int idx = rep * 256 + tid;
        int i  = idx >> 4;
        int j4 = (idx & 15) * 4;
        float4 q = *(const float4*)(g_qp + rowbase + (size_t)i * DM + j4);
        *(float4*)&Qs[i * 68 + j4] = q;
        float4 p = *(const float4*)(Sp + idx * 4);
        int d = (idx * 4) >> 6;
        int kk = (idx * 4) & 63;
        *(float4*)&Ps[d * 68 + kk] = p;
    }
#pragma unroll
    for (int rep = 0; rep < 2; rep++) {
        int idx = rep * 256 + tid;      // 0..511
        int i  = idx >> 3;
        int j8 = (idx & 7) * 8;
        uint4 ku = *(const uint4*)(g_kh + rowbase + (size_t)i * DM + j8);
        uint4 vu = *(const uint4*)(g_vh + rowbase + (size_t)i * DM + j8);
        const __half2* kh2 = (const __half2*)&ku;
        const __half2* vh2 = (const __half2*)&vu;
#pragma unroll
        for (int t = 0; t < 4; t++) {
            float2 kf = __half22float2(kh2[t]);
            float2 vf = __half22float2(vh2[t]);
            Kt[(j8 + t * 2 + 0) * 68 + i] = kf.x;
            Kt[(j8 + t * 2 + 1) * 68 + i] = kf.y;
            Vs[i * 68 + j8 + t * 2 + 0] = vf.x;
            Vs[i * 68 + j8 + t * 2 + 1] = vf.y;
        }
    }
    __syncthreads();

    const int ti = (tid >> 4) * 4;
    const int tj = (tid & 15) * 4;

    float accO[4][4];
    float at[4][4];
#pragma unroll
    for (int a = 0; a < 4; a++)
#pragma unroll
        for (int b = 0; b < 4; b++) { accO[a][b] = 0.f; at[a][b] = 0.f; }

    for (int d = 0; d < 64; d++) {
        float qa[4];
        qa[0] = Qs[(ti + 0) * 68 + d]; qa[1] = Qs[(ti + 1) * 68 + d];
        qa[2] = Qs[(ti + 2) * 68 + d]; qa[3] = Qs[(ti + 3) * 68 + d];
        float4 pp = *(const float4*)&Ps[d * 68 + tj];
        float4 kb = *(const float4*)&Kt[d * 68 + tj];
        float pb[4] = {pp.x, pp.y, pp.z, pp.w};
        float kv[4] = {kb.x, kb.y, kb.z, kb.w};
#pragma unroll
        for (int a = 0; a < 4; a++)
#pragma unroll
            for (int b = 0; b < 4; b++) {
                accO[a][b] = fmaf(qa[a], pb[b], accO[a][b]);
                at[a][b]   = fmaf(qa[a], kv[b], at[a][b]);
            }
    }
#pragma unroll
    for (int a = 0; a < 4; a++)
#pragma unroll
        for (int b = 0; b < 4; b++)
            if (tj + b > ti + a) at[a][b] = 0.f;

    __syncthreads();

    float* As = Ps;
    float* Zc = Kt;
#pragma unroll
    for (int a = 0; a < 4; a++) {
        float4 o; o.x = at[a][0]; o.y = at[a][1]; o.z = at[a][2]; o.w = at[a][3];
        *(float4*)&As[(ti + a) * 68 + tj] = o;
    }
    if (tid < 64) {
        float z = g_qs[((size_t)nh * NC + c) * HD + tid];
        for (int i = 0; i < 64; i++) {
            z += Qs[i * 68 + tid];
            Zc[i * 68 + tid] = z;
        }
    }
    __syncthreads();

    for (int j = 0; j < 64; j++) {
        float aa[4];
        aa[0] = As[(ti + 0) * 68 + j]; aa[1] = As[(ti + 1) * 68 + j];
        aa[2] = As[(ti + 2) * 68 + j]; aa[3] = As[(ti + 3) * 68 + j];
        float4 vv = *(const float4*)&Vs[j * 68 + tj];
        float vb[4] = {vv.x, vv.y, vv.z, vv.w};
#pragma unroll
        for (int a = 0; a < 4; a++)
#pragma unroll
            for (int b = 0; b < 4; b++)
                accO[a][b] = fmaf(aa[a], vb[b], accO[a][b]);
    }

#pragma unroll
    for (int a = 0; a < 4; a++) {
        float4 z4 = *(const float4*)&Zc[(ti + a) * 68 + tj];
        __half2 h01 = __floats2half2_rn(accO[a][0] / z4.x, accO[a][1] / z4.y);
        __half2 h23 = __floats2half2_rn(accO[a][2] / z4.z, accO[a][3] / z4.w);
        size_t eo = rowbase + (size_t)(ti + a) * DM + tj;
        *(__half2*)(g_Ah + eo)     = h01;
        *(__half2*)(g_Ah + eo + 2) = h23;
    }
}

// ---------------------------------------------------------------------------
extern "C" void kernel_launch(void* const* d_in, const int* in_sizes, int n_in,
                              void* d_out, int out_size)
{
    const float* queries = (const float*)d_in[0];
    const float* keys    = (const float*)d_in[1];
    const float* values  = (const float*)d_in[2];
    const float* Wq = (const float*)d_in[3];
    const float* bq = (const float*)d_in[4];
    const float* Wk = (const float*)d_in[5];
    const float* bk = (const float*)d_in[6];
    const float* Wv = (const float*)d_in[7];
    const float* bv = (const float*)d_in[8];
    const float* Wo = (const float*)d_in[9];
    const float* bo = (const float*)d_in[10];
    float* out = (float*)d_out;

    float* qp;  cudaGetSymbolAddress((void**)&qp,  g_qp);
    __half* kh;  cudaGetSymbolAddress((void**)&kh,  g_kh);
    __half* vh;  cudaGetSymbolAddress((void**)&vh,  g_vh);
    __half* ah;  cudaGetSymbolAddress((void**)&ah,  g_Ah);
    __half* whi; cudaGetSymbolAddress((void**)&whi, g_Whi);
    __half* wlo; cudaGetSymbolAddress((void**)&wlo, g_Wlo);

    static bool attrSet = false;
    if (!attrSet) {
        cudaFuncSetAttribute(gemm_f16, cudaFuncAttributeMaxDynamicSharedMemorySize,
                             GEMM_SMEM);
        cudaFuncSetAttribute(chunk_out_kernel,
                             cudaFuncAttributeMaxDynamicSharedMemorySize,
                             CO_SMEM);
        attrSet = true;
    }

    const int splitBlocks = (MROWS * DM / 4 + 255) / 256;

    // Split inputs and all 4 weights (batched)
    split_input3<<<dim3(splitBlocks, 3), 256>>>(queries, keys, values,
                                                MROWS * DM / 4);
    transpose_split4<<<dim3(DM / 32, DM / 32, 4), 256>>>(Wq, Wk, Wv, Wo);

    // Fused Q/K/V projections. Q,K single-term fp16 (loMask bit clear);
    // V 2-term (bit 2 set). q -> fp32 g_qp, k/v -> fp16 g_kh/g_vh.
    gemm_f16<<<dim3(DM / 128, MROWS / 128, 3), 256, GEMM_SMEM>>>(
        ah, whi, wlo, bq, bk, bv, qp, kh, vh, 0x3, 0x6, 0x4);

    // Chunked causal linear attention
    dim3 chunkGrid(NC, NH);
    chunk_sums_kernel<<<chunkGrid, 256>>>();
    prefix_kernel<<<dim3(NH, 8), 256>>>();
    chunk_out_kernel<<<chunkGrid, 256, CO_SMEM>>>();

    // Output projection: 2-term (loMask bit 0 set), fp32 out
    gemm_f16<<<dim3(DM / 128, MROWS / 128, 1), 256, GEMM_SMEM>>>(
        ah, whi + 3 * (size_t)DM * DM, wlo + 3 * (size_t)DM * DM,
        bo, bo, bo, out, kh, vh, 0x0, 0x0, 0x1);
}

// round 9
// speedup vs baseline: 4.4548x; 1.3427x over previous
#include <cuda_runtime.h>
#include <cuda_fp16.h>
#include <math.h>
#include <cstdint>

// Problem constants
#define NB 4
#define LSEQ 2048
#define DM 1024
#define NHEAD 16
#define HD 64
#define MROWS (NB * LSEQ)   // 8192
#define CH 64
#define NC (LSEQ / CH)      // 32
#define NH (NB * NHEAD)     // 64

// Scratch (device globals; no allocation allowed)
__device__ float g_qp[MROWS * DM];          // elu(q)+1 fp32 (needed for Z)
__device__ __half g_kh[MROWS * DM];         // elu(k)+1 fp16
__device__ __half g_vh[MROWS * DM];         // v projection fp16
__device__ float g_S [NH * NC * HD * HD];
__device__ float g_qs[NH * NC * HD];

// fp16 GEMM operand scratch
__device__ __half g_Ah[3 * MROWS * DM];     // q,k,v inputs (att reuses slot 0)
__device__ __half g_W [4 * DM * DM];        // transposed [n][k]; slot 3 = Wo

// ---------------------------------------------------------------------------
// PTX helpers
// ---------------------------------------------------------------------------
__device__ __forceinline__ uint32_t smem_u32(const void* p) {
    uint32_t a;
    asm("{ .reg .u64 t; cvta.to.shared.u64 t, %1; cvt.u32.u64 %0, t; }"
        : "=r"(a) : "l"(p));
    return a;
}

#define CPASYNC16(s, g) \
    asm volatile("cp.async.cg.shared.global [%0], [%1], 16;" \
                 :: "r"(s), "l"(g) : "memory")
#define CPCOMMIT() asm volatile("cp.async.commit_group;" ::: "memory")
#define CPWAIT1()  asm volatile("cp.async.wait_group 1;" ::: "memory")
#define CPWAIT0()  asm volatile("cp.async.wait_group 0;" ::: "memory")

__device__ __forceinline__ void ldsm4(uint32_t* r, uint32_t a) {
    asm volatile("ldmatrix.sync.aligned.m8n8.x4.shared.b16 {%0,%1,%2,%3}, [%4];"
        : "=r"(r[0]), "=r"(r[1]), "=r"(r[2]), "=r"(r[3]) : "r"(a));
}
__device__ __forceinline__ void ldsm2(uint32_t* r, uint32_t a) {
    asm volatile("ldmatrix.sync.aligned.m8n8.x2.shared.b16 {%0,%1}, [%2];"
        : "=r"(r[0]), "=r"(r[1]) : "r"(a));
}
__device__ __forceinline__ void mma16816(float* c, const uint32_t* a, const uint32_t* b) {
    asm volatile("mma.sync.aligned.m16n8k16.row.col.f32.f16.f16.f32 "
        "{%0,%1,%2,%3}, {%4,%5,%6,%7}, {%8,%9}, {%0,%1,%2,%3};"
        : "+f"(c[0]), "+f"(c[1]), "+f"(c[2]), "+f"(c[3])
        : "r"(a[0]), "r"(a[1]), "r"(a[2]), "r"(a[3]), "r"(b[0]), "r"(b[1]));
}

// ---------------------------------------------------------------------------
// split_input3: fp32 -> fp16, batched over z = {q,k,v}
// ---------------------------------------------------------------------------
__global__ void __launch_bounds__(256) split_input3(
    const float* __restrict__ Xq, const float* __restrict__ Xk,
    const float* __restrict__ Xv, int n4)
{
    int z = blockIdx.y;
    const float* X = (z == 0) ? Xq : (z == 1) ? Xk : Xv;
    __half* out = g_Ah + (size_t)z * MROWS * DM;
    int idx = blockIdx.x * 256 + threadIdx.x;
    if (idx >= n4) return;
    float4 x = ((const float4*)X)[idx];
    __half2* op = (__half2*)out;
    op[idx * 2 + 0] = __floats2half2_rn(x.x, x.y);
    op[idx * 2 + 1] = __floats2half2_rn(x.z, x.w);
}

// transpose4: W[k][n] fp32 -> Wt fp16 [n][k], batched over 4 weights
__global__ void __launch_bounds__(256) transpose4(
    const float* __restrict__ W0, const float* __restrict__ W1,
    const float* __restrict__ W2, const float* __restrict__ W3)
{
    __shared__ float t[32][33];
    int z = blockIdx.z;
    const float* W = (z == 0) ? W0 : (z == 1) ? W1 : (z == 2) ? W2 : W3;
    __half* hi = g_W + (size_t)z * DM * DM;
    int bx = blockIdx.x * 32;   // n base
    int by = blockIdx.y * 32;   // k base
    int tx = threadIdx.x & 31;
    int ty = threadIdx.x >> 5;  // 0..7
#pragma unroll
    for (int i = 0; i < 4; i++) {
        int k = by + ty + i * 8;
        t[ty + i * 8][tx] = W[(size_t)k * DM + bx + tx];
    }
    __syncthreads();
#pragma unroll
    for (int i = 0; i < 4; i++) {
        int n = bx + ty + i * 8;
        int k = by + tx;
        hi[(size_t)n * DM + k] = __float2half_rn(t[tx][ty + i * 8]);
    }
}

// ---------------------------------------------------------------------------
// fp16 single-term GEMM: C = A @ W + bias (+elu+1)
// BM=BN=128, BK=32, 256 threads, warp tile 64x32, cp.async 2-stage, 2 CTA/SM.
// ---------------------------------------------------------------------------
#define ARR 10240            // 128 rows * 80B
#define STG (2 * ARR)        // 20480 per stage
#define GEMM_SMEM (2 * STG)  // 40960

__device__ __forceinline__ void load_stage(
    uint32_t sbase, int tid, int k0,
    const __half* pA, const __half* pW)
{
#pragma unroll
    for (int rep = 0; rep < 2; rep++) {
        int l = rep * 256 + tid;        // 0..511
        int row = l >> 2;               // 0..127
        int ch = l & 3;                 // 0..3 (16B chunks)
        uint32_t so = sbase + (uint32_t)row * 80 + ch * 16;
        size_t go = (size_t)row * DM + k0 + ch * 8;
        CPASYNC16(so + 0 * ARR, pA + go);
        CPASYNC16(so + 1 * ARR, pW + go);
    }
}

__global__ void __launch_bounds__(256, 2) gemm_f16(
    const __half* __restrict__ Ah, const __half* __restrict__ W,
    const float* __restrict__ b0, const float* __restrict__ b1,
    const float* __restrict__ b2,
    float* __restrict__ C0, __half* __restrict__ H1, __half* __restrict__ H2,
    int actMask, int halfMask)
{
    extern __shared__ char smem[];
    const uint32_t sb = smem_u32(smem);
    const int z = blockIdx.z;
    const int tid = threadIdx.x;
    const int wid = tid >> 5;
    const int lid = tid & 31;
    const int rowBase = blockIdx.y * 128;
    const int colBase = blockIdx.x * 128;
    const int warpM = (wid >> 2) * 64;
    const int warpN = (wid & 3) * 32;

    const float* bias = (z == 0) ? b0 : (z == 1) ? b1 : b2;
    const int act = (actMask >> z) & 1;
    const int hout = (halfMask >> z) & 1;

    const __half* pA = Ah + (size_t)z * MROWS * DM + (size_t)rowBase * DM;
    const __half* pW = W  + (size_t)z * DM * DM + (size_t)colBase * DM;

    float acc[4][4][4];
#pragma unroll
    for (int i = 0; i < 4; i++)
#pragma unroll
        for (int j = 0; j < 4; j++)
#pragma unroll
            for (int e = 0; e < 4; e++) acc[i][j][e] = 0.f;

    load_stage(sb, tid, 0, pA, pW);
    CPCOMMIT();

    const int aRow = warpM + (lid & 15);
    const uint32_t aCol = ((lid >> 4) & 1) * 16;
    const int bRow = warpN + (lid & 7);
    const uint32_t bCol = ((lid >> 3) & 1) * 16;

    for (int c = 0; c < 32; c++) {
        if (c + 1 < 32) {
            load_stage(sb + ((c + 1) & 1) * STG, tid, (c + 1) * 32, pA, pW);
            CPCOMMIT();
            CPWAIT1();
        } else {
            CPWAIT0();
        }
        __syncthreads();

        const uint32_t stage = sb + (c & 1) * STG;
#pragma unroll
        for (int kk = 0; kk < 2; kk++) {
            const uint32_t aOff = (uint32_t)kk * 32 + aCol;
            const uint32_t bOff = (uint32_t)kk * 32 + bCol;
            uint32_t fB[4][2];
#pragma unroll
            for (int ni = 0; ni < 4; ni++)
                ldsm2(fB[ni], stage + (uint32_t)(bRow + ni * 8) * 80 + bOff + 1 * ARR);
#pragma unroll
            for (int mi = 0; mi < 4; mi++) {
                uint32_t fA[4];
                ldsm4(fA, stage + (uint32_t)(aRow + mi * 16) * 80 + aOff);
#pragma unroll
                for (int ni = 0; ni < 4; ni++)
                    mma16816(acc[mi][ni], fA, fB[ni]);
            }
        }
        __syncthreads();
    }

    // epilogue
    __half* H = (z == 1) ? H1 : H2;
#pragma unroll
    for (int mi = 0; mi < 4; mi++) {
        int r0 = rowBase + warpM + mi * 16 + (lid >> 2);
#pragma unroll
        for (int ni = 0; ni < 4; ni++) {
            int col = colBase + warpN + ni * 8 + (lid & 3) * 2;
            float2 b2v = *(const float2*)(bias + col);
            float v0 = acc[mi][ni][0] + b2v.x;
            float v1 = acc[mi][ni][1] + b2v.y;
            float v2 = acc[mi][ni][2] + b2v.x;
            float v3 = acc[mi][ni][3] + b2v.y;
            if (act) {
                v0 = (v0 > 0.f) ? (v0 + 1.f) : expf(v0);
                v1 = (v1 > 0.f) ? (v1 + 1.f) : expf(v1);
                v2 = (v2 > 0.f) ? (v2 + 1.f) : expf(v2);
                v3 = (v3 > 0.f) ? (v3 + 1.f) : expf(v3);
            }
            if (hout) {
                *(__half2*)(H + (size_t)r0 * DM + col)       = __floats2half2_rn(v0, v1);
                *(__half2*)(H + (size_t)(r0 + 8) * DM + col) = __floats2half2_rn(v2, v3);
            } else {
                float2 o0; o0.x = v0; o0.y = v1;
                float2 o1; o1.x = v2; o1.y = v3;
                *(float2*)(C0 + (size_t)r0 * DM + col) = o0;
                *(float2*)(C0 + (size_t)(r0 + 8) * DM + col) = o1;
            }
        }
    }
}

// ---------------------------------------------------------------------------
// Attention kernels
// ---------------------------------------------------------------------------
__global__ void __launch_bounds__(256) chunk_sums_kernel()
{
    const int c = blockIdx.x;
    const int nh = blockIdx.y;
    const int n = nh >> 4;
    const int h = nh & 15;
    const int tid = threadIdx.x;

    __shared__ float Ks[64][68];
    __shared__ float Vs[64][68];
    __shared__ float qsum[4][72];

    const size_t rowbase = ((size_t)(n * LSEQ + c * CH)) * DM + h * HD;

    {
        int col = tid & 63;
        int qtr = tid >> 6;     // 0..3
        float s = 0.f;
        const float* qb = g_qp + rowbase + (size_t)(qtr * 16) * DM + col;
#pragma unroll
        for (int i = 0; i < 16; i++)
            s += qb[(size_t)i * DM];
        qsum[qtr][col] = s;
    }

#pragma unroll
    for (int rep = 0; rep < 2; rep++) {
        int idx = rep * 256 + tid;      // 0..511
        int i  = idx >> 3;              // row
        int j8 = (idx & 7) * 8;         // col base
        uint4 ku = *(const uint4*)(g_kh + rowbase + (size_t)i * DM + j8);
        uint4 vu = *(const uint4*)(g_vh + rowbase + (size_t)i * DM + j8);
        const __half2* kh2 = (const __half2*)&ku;
        const __half2* vh2 = (const __half2*)&vu;
#pragma unroll
        for (int t = 0; t < 4; t++) {
            float2 kf = __half22float2(kh2[t]);
            float2 vf = __half22float2(vh2[t]);
            Ks[i][j8 + t * 2 + 0] = kf.x;
            Ks[i][j8 + t * 2 + 1] = kf.y;
            Vs[i][j8 + t * 2 + 0] = vf.x;
            Vs[i][j8 + t * 2 + 1] = vf.y;
        }
    }
    __syncthreads();

    const int td = (tid >> 4) * 4;
    const int tk = (tid & 15) * 4;
    float acc[4][4];
#pragma unroll
    for (int a = 0; a < 4; a++)
#pragma unroll
        for (int b = 0; b < 4; b++) acc[a][b] = 0.f;

    for (int i = 0; i < 64; i++) {
        float ka[4];
        ka[0] = Ks[i][td + 0]; ka[1] = Ks[i][td + 1];
        ka[2] = Ks[i][td + 2]; ka[3] = Ks[i][td + 3];
        float4 vv = *(const float4*)&Vs[i][tk];
        float vb[4] = {vv.x, vv.y, vv.z, vv.w};
#pragma unroll
        for (int a = 0; a < 4; a++)
#pragma unroll
            for (int b = 0; b < 4; b++)
                acc[a][b] = fmaf(ka[a], vb[b], acc[a][b]);
    }

    float* Sp = g_S + ((size_t)nh * NC + c) * (HD * HD);
#pragma unroll
    for (int a = 0; a < 4; a++) {
        float4 o; o.x=acc[a][0]; o.y=acc[a][1]; o.z=acc[a][2]; o.w=acc[a][3];
        *(float4*)&Sp[(td + a) * HD + tk] = o;
    }

    if (tid < 64) {
        float s = qsum[0][tid] + qsum[1][tid] + qsum[2][tid] + qsum[3][tid];
        g_qs[((size_t)nh * NC + c) * HD + tid] = s;
    }
}

// Parallel prefix: grid (NH, 8), 256 threads; each thread scans 2 elements.
__global__ void __launch_bounds__(256) prefix_kernel()
{
    const int nh = blockIdx.x;
    const int seg = blockIdx.y;     // 0..7
    const int tid = threadIdx.x;
    const int e0 = seg * 512 + tid;

    float r0 = 0.f, r1 = 0.f;
    for (int c = 0; c < NC; c++) {
        float* Sp = g_S + ((size_t)nh * NC + c) * (HD * HD);
        float t0 = Sp[e0];       Sp[e0] = r0;       r0 += t0;
        float t1 = Sp[e0 + 256]; Sp[e0 + 256] = r1; r1 += t1;
    }

    if (seg == 0 && tid < 64) {
        float r = 0.f;
        for (int c = 0; c < NC; c++) {
            float* qp = g_qs + ((size_t)nh * NC + c) * HD + tid;
            float t = *qp;
            *qp = r;
            r += t;
        }
    }
}

// chunk_out: O = (tril(Qp Kp^T) V + Qp P) / Z, fp16 out into g_Ah[0].
#define TS (64 * 68)
#define CO_SMEM (4 * TS * 4)   // 69632 bytes
__global__ void __launch_bounds__(256, 2) chunk_out_kernel()
{
    extern __shared__ float fsm[];
    float* Qs = fsm;            // [i][d]
    float* Kt = fsm + TS;       // [d][i]  -> Zc later
    float* Vs = fsm + 2 * TS;   // [j][k]
    float* Ps = fsm + 3 * TS;   // [d][k]  -> As later

    const int c = blockIdx.x;
    const int nh = blockIdx.y;
    const int n = nh >> 4;
    const int h = nh & 15;
    const int tid = threadIdx.x;

    const size_t rowbase = ((size_t)(n * LSEQ + c * CH)) * DM + h * HD;
    const float* Sp = g_S + ((size_t)nh * NC + c) * (HD * HD);

#pragma unroll
    for (int rep = 0; rep < 4; rep++) {
        int idx = rep * 256 + tid;
        int i  = idx >> 4;
        int j4 = (idx & 15) * 4;
        float4 q = *(const float4*)(g_qp + rowbase + (size_t)i * DM + j4);
        *(float4*)&Qs[i * 68 + j4] = q;
        float4 p = *(const float4*)(Sp + idx * 4);
        int d = (idx * 4) >> 6;
        int kk = (idx * 4) & 63;
        *(float4*)&Ps[d * 68 + kk] = p;
    }
#pragma unroll
    for (int rep = 0; rep < 2; rep++) {
        int idx = rep * 256 + tid;      // 0..511
        int i  = idx >> 3;
        int j8 = (idx & 7) * 8;
        uint4 ku = *(const uint4*)(g_kh + rowbase + (size_t)i * DM + j8);
        uint4 vu = *(const uint4*)(g_vh + rowbase + (size_t)i * DM + j8);
        const __half2* kh2 = (const __half2*)&ku;
        const __half2* vh2 = (const __half2*)&vu;
#pragma unroll
        for (int t = 0; t < 4; t++) {
            float2 kf = __half22float2(kh2[t]);
            float2 vf = __half22float2(vh2[t]);
            Kt[(j8 + t * 2 + 0) * 68 + i] = kf.x;
            Kt[(j8 + t * 2 + 1) * 68 + i] = kf.y;
            Vs[i * 68 + j8 + t * 2 + 0] = vf.x;
            Vs[i * 68 + j8 + t * 2 + 1] = vf.y;
        }
    }
    __syncthreads();

    const int ti = (tid >> 4) * 4;
    const int tj = (tid & 15) * 4;

    float accO[4][4];
    float at[4][4];
#pragma unroll
    for (int a = 0; a < 4; a++)
#pragma unroll
        for (int b = 0; b < 4; b++) { accO[a][b] = 0.f; at[a][b] = 0.f; }

    for (int d = 0; d < 64; d++) {
        float qa[4];
        qa[0] = Qs[(ti + 0) * 68 + d]; qa[1] = Qs[(ti + 1) * 68 + d];
        qa[2] = Qs[(ti + 2) * 68 + d]; qa[3] = Qs[(ti + 3) * 68 + d];
        float4 pp = *(const float4*)&Ps[d * 68 + tj];
        float4 kb = *(const float4*)&Kt[d * 68 + tj];
        float pb[4] = {pp.x, pp.y, pp.z, pp.w};
        float kv[4] = {kb.x, kb.y, kb.z, kb.w};
#pragma unroll
        for (int a = 0; a < 4; a++)
#pragma unroll
            for (int b = 0; b < 4; b++) {
                accO[a][b] = fmaf(qa[a], pb[b], accO[a][b]);
                at[a][b]   = fmaf(qa[a], kv[b], at[a][b]);
            }
    }
#pragma unroll
    for (int a = 0; a < 4; a++)
#pragma unroll
        for (int b = 0; b < 4; b++)
            if (tj + b > ti + a) at[a][b] = 0.f;

    __syncthreads();

    float* As = Ps;
    float* Zc = Kt;
#pragma unroll
    for (int a = 0; a < 4; a++) {
        float4 o; o.x = at[a][0]; o.y = at[a][1]; o.z = at[a][2]; o.w = at[a][3];
        *(float4*)&As[(ti + a) * 68 + tj] = o;
    }
    if (tid < 64) {
        float z = g_qs[((size_t)nh * NC + c) * HD + tid];
        for (int i = 0; i < 64; i++) {
            z += Qs[i * 68 + tid];
            Zc[i * 68 + tid] = z;
        }
    }
    __syncthreads();

    for (int j = 0; j < 64; j++) {
        float aa[4];
        aa[0] = As[(ti + 0) * 68 + j]; aa[1] = As[(ti + 1) * 68 + j];
        aa[2] = As[(ti + 2) * 68 + j]; aa[3] = As[(ti + 3) * 68 + j];
        float4 vv = *(const float4*)&Vs[j * 68 + tj];
        float vb[4] = {vv.x, vv.y, vv.z, vv.w};
#pragma unroll
        for (int a = 0; a < 4; a++)
#pragma unroll
            for (int b = 0; b < 4; b++)
                accO[a][b] = fmaf(aa[a], vb[b], accO[a][b]);
    }

#pragma unroll
    for (int a = 0; a < 4; a++) {
        float4 z4 = *(const float4*)&Zc[(ti + a) * 68 + tj];
        __half2 h01 = __floats2half2_rn(accO[a][0] / z4.x, accO[a][1] / z4.y);
        __half2 h23 = __floats2half2_rn(accO[a][2] / z4.z, accO[a][3] / z4.w);
        size_t eo = rowbase + (size_t)(ti + a) * DM + tj;
        *(__half2*)(g_Ah + eo)     = h01;
        *(__half2*)(g_Ah + eo + 2) = h23;
    }
}

// ---------------------------------------------------------------------------
extern "C" void kernel_launch(void* const* d_in, const int* in_sizes, int n_in,
                              void* d_out, int out_size)
{
    const float* queries = (const float*)d_in[0];
    const float* keys    = (const float*)d_in[1];
    const float* values  = (const float*)d_in[2];
    const float* Wq = (const float*)d_in[3];
    const float* bq = (const float*)d_in[4];
    const float* Wk = (const float*)d_in[5];
    const float* bk = (const float*)d_in[6];
    const float* Wv = (const float*)d_in[7];
    const float* bv = (const float*)d_in[8];
    const float* Wo = (const float*)d_in[9];
    const float* bo = (const float*)d_in[10];
    float* out = (float*)d_out;

    float* qp;  cudaGetSymbolAddress((void**)&qp,  g_qp);
    __half* kh; cudaGetSymbolAddress((void**)&kh,  g_kh);
    __half* vh; cudaGetSymbolAddress((void**)&vh,  g_vh);
    __half* ah; cudaGetSymbolAddress((void**)&ah,  g_Ah);
    __half* w;  cudaGetSymbolAddress((void**)&w,   g_W);

    static bool attrSet = false;
    if (!attrSet) {
        cudaFuncSetAttribute(gemm_f16, cudaFuncAttributeMaxDynamicSharedMemorySize,
                             GEMM_SMEM);
        cudaFuncSetAttribute(chunk_out_kernel,
                             cudaFuncAttributeMaxDynamicSharedMemorySize,
                             CO_SMEM);
        attrSet = true;
    }

    const int splitBlocks = (MROWS * DM / 4 + 255) / 256;

    // Split inputs and all 4 weights (batched, single-term fp16)
    split_input3<<<dim3(splitBlocks, 3), 256>>>(queries, keys, values,
                                                MROWS * DM / 4);
    transpose4<<<dim3(DM / 32, DM / 32, 4), 256>>>(Wq, Wk, Wv, Wo);

    // Fused Q/K/V projections: q -> fp32 g_qp, k/v -> fp16 g_kh/g_vh
    gemm_f16<<<dim3(DM / 128, MROWS / 128, 3), 256, GEMM_SMEM>>>(
        ah, w, bq, bk, bv, qp, kh, vh, 0x3, 0x6);

    // Chunked causal linear attention
    dim3 chunkGrid(NC, NH);
    chunk_sums_kernel<<<chunkGrid, 256>>>();
    prefix_kernel<<<dim3(NH, 8), 256>>>();
    chunk_out_kernel<<<chunkGrid, 256, CO_SMEM>>>();

    // Output projection: att (slot 0 of g_Ah) @ Wo (slot 3) + bo -> fp32 out
    gemm_f16<<<dim3(DM / 128, MROWS / 128, 1), 256, GEMM_SMEM>>>(
        ah, w + 3 * (size_t)DM * DM, bo, bo, bo, out, kh, vh, 0x0, 0x0);
}